// round 1
// baseline (speedup 1.0000x reference)
#include <cuda_runtime.h>
#include <math.h>

#define BB 2
#define TT 2048
#define EE 1024
#define HH 16
#define DH 64
#define MM (BB*TT)   // 4096

// Scratch (allocations are forbidden; __device__ globals are the sanctioned path)
__device__ float g_q [MM*EE];
__device__ float g_k [MM*EE];
__device__ float g_v [MM*EE];
__device__ float g_x1[MM*EE];

// ---------------------------------------------------------------------------
// Tiled fp32 GEMM: C[M,1024] = A[M,1024] @ W[1024,1024]
// BM=BN=64, BK=16, 256 threads, 4x4 per thread.
// EPI==0: plain store. EPI==1: C = A + relu(acc + bias)   (FFN w/ residual)
// ---------------------------------------------------------------------------
template<int EPI>
__global__ void __launch_bounds__(256) gemm_kernel(const float* __restrict__ A,
                                                   const float* __restrict__ W,
                                                   float* __restrict__ C,
                                                   const float* __restrict__ bias)
{
    __shared__ float As[16][68];   // transposed: As[k][m]
    __shared__ float Ws[16][64];   // natural:    Ws[k][n]
    const int tid = threadIdx.x;
    const int tx = tid & 15, ty = tid >> 4;
    const int row0 = blockIdx.y * 64;
    const int col0 = blockIdx.x * 64;

    float acc[4][4] = {};

    for (int k0 = 0; k0 < EE; k0 += 16) {
        {
            int m  = tid >> 2;           // 0..63
            int kk = (tid & 3) << 2;     // 0,4,8,12
            float4 va = *reinterpret_cast<const float4*>(&A[(row0 + m) * EE + k0 + kk]);
            As[kk+0][m] = va.x; As[kk+1][m] = va.y;
            As[kk+2][m] = va.z; As[kk+3][m] = va.w;
            int kw = tid >> 4;           // 0..15
            int n  = (tid & 15) << 2;    // 0..60
            *reinterpret_cast<float4*>(&Ws[kw][n]) =
                *reinterpret_cast<const float4*>(&W[(k0 + kw) * EE + col0 + n]);
        }
        __syncthreads();
        #pragma unroll
        for (int kk = 0; kk < 16; kk++) {
            float4 a4 = *reinterpret_cast<const float4*>(&As[kk][ty << 2]);
            float4 b4 = *reinterpret_cast<const float4*>(&Ws[kk][tx << 2]);
            float av[4] = {a4.x, a4.y, a4.z, a4.w};
            float bv[4] = {b4.x, b4.y, b4.z, b4.w};
            #pragma unroll
            for (int i = 0; i < 4; i++)
                #pragma unroll
                for (int j = 0; j < 4; j++)
                    acc[i][j] = fmaf(av[i], bv[j], acc[i][j]);
        }
        __syncthreads();
    }

    #pragma unroll
    for (int i = 0; i < 4; i++) {
        int r = row0 + (ty << 2) + i;
        #pragma unroll
        for (int j = 0; j < 4; j++) {
            int c = col0 + (tx << 2) + j;
            if (EPI == 0) {
                C[r * EE + c] = acc[i][j];
            } else {
                float x1 = A[r * EE + c];
                float y  = acc[i][j] + bias[c];
                C[r * EE + c] = x1 + fmaxf(y, 0.f);
            }
        }
    }
}

// ---------------------------------------------------------------------------
// Flash attention (causal, online softmax).
// One CTA = one (b,h,q-tile of 64). dh = 64, K tile = 64. 256 threads (16x16),
// each owning a 4x4 micro-tile of S/P and of O.
// Epilogue fuses the residual: g_x1 = x + attn.
// ---------------------------------------------------------------------------
__global__ void __launch_bounds__(256) attn_kernel(const float* __restrict__ x)
{
    extern __shared__ float sm[];
    float* Qt   = sm;              // [64][68]  Qt[d][q]   (transposed)
    float* KtP  = Qt  + 64*68;     // [64][68]  Kt[d][k] -> then Ps[q][k]
    float* Vs   = KtP + 64*68;     // [64][68]  Vs[k][d]   (natural)
    float* red  = Vs  + 64*68;     // [64][16]  row reduction scratch
    float* m_sm = red + 64*16;     // [64]
    float* l_sm = m_sm + 64;       // [64]
    float* c_sm = l_sm + 64;       // [64]

    const int tid = threadIdx.x;
    const int tx = tid & 15, ty = tid >> 4;
    const int bh = blockIdx.y;
    const int b  = bh / HH, h = bh % HH;
    const int qt = blockIdx.x;
    const float scale = 0.03125f;  // 1/sqrt(1024)

    const int base_q = (b * TT + qt * 64) * EE + h * DH;

    // Load Q transposed: Qt[d][q]
    #pragma unroll
    for (int rep = 0; rep < 4; rep++) {
        int r = (tid >> 4) + rep * 16;
        int d = (tid & 15) << 2;
        float4 v4 = *reinterpret_cast<const float4*>(&g_q[base_q + r * EE + d]);
        Qt[(d+0)*68 + r] = v4.x;
        Qt[(d+1)*68 + r] = v4.y;
        Qt[(d+2)*68 + r] = v4.z;
        Qt[(d+3)*68 + r] = v4.w;
    }
    if (tid < 64) { m_sm[tid] = -3.0e38f; l_sm[tid] = 0.f; }

    float o[4][4] = {};

    for (int kt = 0; kt <= qt; kt++) {
        __syncthreads();   // protect KtP/Vs/red/c_sm from prior iteration consumers
        const int base_k = (b * TT + kt * 64) * EE + h * DH;
        #pragma unroll
        for (int rep = 0; rep < 4; rep++) {
            int r = (tid >> 4) + rep * 16;
            int d = (tid & 15) << 2;
            float4 k4 = *reinterpret_cast<const float4*>(&g_k[base_k + r * EE + d]);
            KtP[(d+0)*68 + r] = k4.x;
            KtP[(d+1)*68 + r] = k4.y;
            KtP[(d+2)*68 + r] = k4.z;
            KtP[(d+3)*68 + r] = k4.w;
            float4 v4 = *reinterpret_cast<const float4*>(&g_v[base_k + r * EE + d]);
            *reinterpret_cast<float4*>(&Vs[r*68 + d]) = v4;
        }
        __syncthreads();

        // S = Q K^T (64x64x64)
        float s[4][4] = {};
        #pragma unroll 8
        for (int d = 0; d < 64; d++) {
            float4 a4 = *reinterpret_cast<const float4*>(&Qt [d*68 + (ty << 2)]);
            float4 b4 = *reinterpret_cast<const float4*>(&KtP[d*68 + (tx << 2)]);
            float av[4] = {a4.x, a4.y, a4.z, a4.w};
            float bv[4] = {b4.x, b4.y, b4.z, b4.w};
            #pragma unroll
            for (int i = 0; i < 4; i++)
                #pragma unroll
                for (int j = 0; j < 4; j++)
                    s[i][j] = fmaf(av[i], bv[j], s[i][j]);
        }

        // scale + causal mask (only the diagonal tile) + partial row max
        const bool diag = (kt == qt);
        #pragma unroll
        for (int i = 0; i < 4; i++) {
            float rm = -3.0e38f;
            #pragma unroll
            for (int j = 0; j < 4; j++) {
                float sv = s[i][j] * scale;
                if (diag && ((tx << 2) + j) > ((ty << 2) + i)) sv = -1.0e30f;
                s[i][j] = sv;
                rm = fmaxf(rm, sv);
            }
            red[((ty << 2) + i) * 16 + tx] = rm;
        }
        __syncthreads();

        if (tid < 64) {
            float mt = red[tid * 16];
            #pragma unroll
            for (int u = 1; u < 16; u++) mt = fmaxf(mt, red[tid * 16 + u]);
            float mn = fmaxf(m_sm[tid], mt);
            c_sm[tid] = __expf(m_sm[tid] - mn);
            m_sm[tid] = mn;
        }
        __syncthreads();

        // P = exp(S - m), rescale O, partial row sums, P -> smem (reusing K buf)
        #pragma unroll
        for (int i = 0; i < 4; i++) {
            int r = (ty << 2) + i;
            float mn = m_sm[r];
            float cr = c_sm[r];
            float rs = 0.f;
            float pv[4];
            #pragma unroll
            for (int j = 0; j < 4; j++) {
                float p = __expf(s[i][j] - mn);
                pv[j] = p;
                rs += p;
                o[i][j] *= cr;
            }
            float4 p4; p4.x = pv[0]; p4.y = pv[1]; p4.z = pv[2]; p4.w = pv[3];
            *reinterpret_cast<float4*>(&KtP[r*68 + (tx << 2)]) = p4;
            red[r * 16 + tx] = rs;
        }
        __syncthreads();

        if (tid < 64) {
            float rs = 0.f;
            #pragma unroll
            for (int u = 0; u < 16; u++) rs += red[tid * 16 + u];
            l_sm[tid] = l_sm[tid] * c_sm[tid] + rs;
        }

        // O += P @ V  (64x64x64)
        #pragma unroll 8
        for (int k = 0; k < 64; k++) {
            float av[4];
            av[0] = KtP[((ty << 2) + 0) * 68 + k];
            av[1] = KtP[((ty << 2) + 1) * 68 + k];
            av[2] = KtP[((ty << 2) + 2) * 68 + k];
            av[3] = KtP[((ty << 2) + 3) * 68 + k];
            float4 b4 = *reinterpret_cast<const float4*>(&Vs[k*68 + (tx << 2)]);
            float bv[4] = {b4.x, b4.y, b4.z, b4.w};
            #pragma unroll
            for (int i = 0; i < 4; i++)
                #pragma unroll
                for (int j = 0; j < 4; j++)
                    o[i][j] = fmaf(av[i], bv[j], o[i][j]);
        }
    }
    __syncthreads();

    // Epilogue: normalize + residual: x1 = x + attn
    #pragma unroll
    for (int i = 0; i < 4; i++) {
        int r = (ty << 2) + i;
        float inv_l = 1.f / l_sm[r];
        #pragma unroll
        for (int j = 0; j < 4; j++) {
            int c = (tx << 2) + j;
            int idx = base_q + r * EE + c;
            g_x1[idx] = x[idx] + o[i][j] * inv_l;
        }
    }
}

// ---------------------------------------------------------------------------
extern "C" void kernel_launch(void* const* d_in, const int* in_sizes, int n_in,
                              void* d_out, int out_size)
{
    const float* x  = (const float*)d_in[0];
    const float* Wq = (const float*)d_in[1];
    const float* Wk = (const float*)d_in[2];
    const float* Wv = (const float*)d_in[3];
    const float* Wf = (const float*)d_in[4];
    const float* bf = (const float*)d_in[5];
    float* out = (float*)d_out;

    float *gq, *gk, *gv, *gx1;
    cudaGetSymbolAddress((void**)&gq,  g_q);
    cudaGetSymbolAddress((void**)&gk,  g_k);
    cudaGetSymbolAddress((void**)&gv,  g_v);
    cudaGetSymbolAddress((void**)&gx1, g_x1);

    dim3 gg(EE / 64, MM / 64);   // (16, 64)

    gemm_kernel<0><<<gg, 256>>>(x, Wq, gq, nullptr);
    gemm_kernel<0><<<gg, 256>>>(x, Wk, gk, nullptr);
    gemm_kernel<0><<<gg, 256>>>(x, Wv, gv, nullptr);

    const int smem_bytes = (3 * 64 * 68 + 64 * 16 + 3 * 64) * (int)sizeof(float); // 57088
    cudaFuncSetAttribute(attn_kernel, cudaFuncAttributeMaxDynamicSharedMemorySize, smem_bytes);
    attn_kernel<<<dim3(TT / 64, BB * HH), 256, smem_bytes>>>(x);

    gemm_kernel<1><<<gg, 256>>>(gx1, Wf, out, bf);
}

// round 4
// speedup vs baseline: 2.8860x; 2.8860x over previous
#include <cuda_runtime.h>
#include <cstdint>
#include <math.h>

#define BB 2
#define TT 2048
#define EE 1024
#define HH 16
#define DH 64
#define MM (BB*TT)   // 4096

// Scratch (__device__ globals; allocations are forbidden)
__device__ float g_q [MM*EE];
__device__ float g_k [MM*EE];
__device__ float g_v [MM*EE];
__device__ float g_x1[MM*EE];

// ---------------------------------------------------------------------------
// Baseline-PTX helpers (sm_80-era features only: mma.sync + cp.async).
// tcgen05/TMEM is rejected by this toolchain (PTX targets compute_103 w/o 'a').
// ---------------------------------------------------------------------------
__device__ __forceinline__ uint32_t smem_u32(const void* p){
    uint32_t a;
    asm("{ .reg .u64 t; cvta.to.shared.u64 t, %1; cvt.u32.u64 %0, t; }":"=r"(a):"l"(p));
    return a;
}
#define CP16(dst,src)  asm volatile("cp.async.cg.shared.global [%0], [%1], 16;\n"::"r"(dst),"l"(src))
#define CP_COMMIT()    asm volatile("cp.async.commit_group;\n":::"memory")
#define CP_WAIT1()     asm volatile("cp.async.wait_group 1;\n":::"memory")
#define CP_WAIT0()     asm volatile("cp.async.wait_group 0;\n":::"memory")

__device__ __forceinline__ void mma_tf32(float c[4], uint32_t a0, uint32_t a1,
                                         uint32_t a2, uint32_t a3,
                                         uint32_t b0, uint32_t b1){
    asm volatile(
        "mma.sync.aligned.m16n8k8.row.col.f32.tf32.tf32.f32 "
        "{%0,%1,%2,%3}, {%4,%5,%6,%7}, {%8,%9}, {%0,%1,%2,%3};\n"
        : "+f"(c[0]), "+f"(c[1]), "+f"(c[2]), "+f"(c[3])
        : "r"(a0), "r"(a1), "r"(a2), "r"(a3), "r"(b0), "r"(b1));
}

// ---------------------------------------------------------------------------
// tf32 mma.sync GEMM:  C[4096,1024] = A[4096,1024] @ W[1024,1024]
// CTA 128x256, BK=32, 8 warps (2 in M x 4 in N), warp tile 64x64.
// Double-buffered smem via cp.async. W used directly as col-major B operand.
// Padded strides: A_ST=36 (≡4 mod 32), B_ST=264 (≡8 mod 32) -> conflict-free
// fragment loads.
// EPI==0: C = acc.   EPI==1: C = A + relu(acc + bias).
// ---------------------------------------------------------------------------
#define A_ST 36
#define B_ST 264
#define A_TILE (128*A_ST)            // 4608 floats
#define B_TILE (32*B_ST)             // 8448 floats
#define STAGE  (A_TILE + B_TILE)     // 13056 floats
#define GEMM_SMEM (2*STAGE*4)        // 104448 bytes

template<int EPI>
__global__ void __launch_bounds__(256) gemm_tc(const float* __restrict__ A,
                                               const float* __restrict__ W,
                                               float* __restrict__ C,
                                               const float* __restrict__ bias)
{
    extern __shared__ float sm[];
    const uint32_t sbase = smem_u32(sm);
    const int tid  = threadIdx.x;
    const int wid  = tid >> 5, lane = tid & 31;
    const int ty   = lane >> 2, tx = lane & 3;    // groupID, thread-in-group
    const int wm   = wid >> 2;                    // 0..1  (M)
    const int wn   = wid & 3;                     // 0..3  (N)
    const int row0 = blockIdx.y * 128;
    const int col0 = blockIdx.x * 256;

    float c[4][8][4];
    #pragma unroll
    for (int mf = 0; mf < 4; mf++)
        #pragma unroll
        for (int nf = 0; nf < 8; nf++)
            #pragma unroll
            for (int u = 0; u < 4; u++) c[mf][nf][u] = 0.f;

    // ---- async tile loader ----
    auto load_tiles = [&](int st, int k0){
        uint32_t sA = sbase + st * (STAGE * 4);
        uint32_t sB = sA + A_TILE * 4;
        #pragma unroll
        for (int t = 0; t < 4; t++) {               // A: 128x32 = 1024 float4
            int s  = tid + t * 256;
            int r  = s >> 3;
            int cf = (s & 7) << 2;
            CP16(sA + (uint32_t)(r * A_ST + cf) * 4,
                 A + (size_t)(row0 + r) * EE + k0 + cf);
        }
        #pragma unroll
        for (int t = 0; t < 8; t++) {               // B: 32x256 = 2048 float4
            int s  = tid + t * 256;
            int r  = s >> 6;
            int cf = (s & 63) << 2;
            CP16(sB + (uint32_t)(r * B_ST + cf) * 4,
                 W + (size_t)(k0 + r) * EE + col0 + cf);
        }
    };

    load_tiles(0, 0);
    CP_COMMIT();

    for (int kt = 0; kt < 32; kt++) {
        const int b = kt & 1;
        if (kt + 1 < 32) {
            load_tiles(1 - b, (kt + 1) << 5);
            CP_COMMIT();
            CP_WAIT1();
        } else {
            CP_WAIT0();
        }
        __syncthreads();

        const float* As = sm + b * STAGE;
        const float* Bs = As + A_TILE;

        #pragma unroll
        for (int ks = 0; ks < 4; ks++) {
            const int k = ks << 3;
            uint32_t a[4][4];
            #pragma unroll
            for (int mf = 0; mf < 4; mf++) {
                const int rb = wm * 64 + mf * 16;
                a[mf][0] = __float_as_uint(As[(rb + ty    ) * A_ST + k + tx    ]);
                a[mf][1] = __float_as_uint(As[(rb + ty + 8) * A_ST + k + tx    ]);
                a[mf][2] = __float_as_uint(As[(rb + ty    ) * A_ST + k + tx + 4]);
                a[mf][3] = __float_as_uint(As[(rb + ty + 8) * A_ST + k + tx + 4]);
            }
            uint32_t bfr[8][2];
            #pragma unroll
            for (int nf = 0; nf < 8; nf++) {
                const int n = wn * 64 + nf * 8 + ty;
                bfr[nf][0] = __float_as_uint(Bs[(k + tx    ) * B_ST + n]);
                bfr[nf][1] = __float_as_uint(Bs[(k + tx + 4) * B_ST + n]);
            }
            #pragma unroll
            for (int mf = 0; mf < 4; mf++)
                #pragma unroll
                for (int nf = 0; nf < 8; nf++)
                    mma_tf32(c[mf][nf], a[mf][0], a[mf][1], a[mf][2], a[mf][3],
                             bfr[nf][0], bfr[nf][1]);
        }
        __syncthreads();
    }

    // ---- epilogue ----
    #pragma unroll
    for (int mf = 0; mf < 4; mf++) {
        const int r = row0 + wm * 64 + mf * 16 + ty;
        #pragma unroll
        for (int nf = 0; nf < 8; nf++) {
            const int cc = col0 + wn * 64 + nf * 8 + (tx << 1);
            float2 v0 = make_float2(c[mf][nf][0], c[mf][nf][1]);
            float2 v1 = make_float2(c[mf][nf][2], c[mf][nf][3]);
            if (EPI == 1) {
                float2 bb = *reinterpret_cast<const float2*>(bias + cc);
                float2 x0 = *reinterpret_cast<const float2*>(A + (size_t)r * EE + cc);
                float2 x1 = *reinterpret_cast<const float2*>(A + (size_t)(r + 8) * EE + cc);
                v0.x = x0.x + fmaxf(v0.x + bb.x, 0.f);
                v0.y = x0.y + fmaxf(v0.y + bb.y, 0.f);
                v1.x = x1.x + fmaxf(v1.x + bb.x, 0.f);
                v1.y = x1.y + fmaxf(v1.y + bb.y, 0.f);
            }
            *reinterpret_cast<float2*>(C + (size_t)r * EE + cc) = v0;
            *reinterpret_cast<float2*>(C + (size_t)(r + 8) * EE + cc) = v1;
        }
    }
}

// ---------------------------------------------------------------------------
// Flash attention (causal, online softmax) — proven R1 SIMT version.
// Epilogue fuses the residual: g_x1 = x + attn.
// ---------------------------------------------------------------------------
__global__ void __launch_bounds__(256) attn_kernel(const float* __restrict__ x)
{
    extern __shared__ float sm[];
    float* Qt   = sm;              // [64][68]
    float* KtP  = Qt  + 64*68;     // [64][68]
    float* Vs   = KtP + 64*68;     // [64][68]
    float* red  = Vs  + 64*68;     // [64][16]
    float* m_sm = red + 64*16;
    float* l_sm = m_sm + 64;
    float* c_sm = l_sm + 64;

    const int tid = threadIdx.x;
    const int tx = tid & 15, ty = tid >> 4;
    const int bh = blockIdx.y;
    const int b  = bh / HH, h = bh % HH;
    const int qt = blockIdx.x;
    const float scale = 0.03125f;

    const int base_q = (b * TT + qt * 64) * EE + h * DH;

    #pragma unroll
    for (int rep = 0; rep < 4; rep++) {
        int r = (tid >> 4) + rep * 16;
        int d = (tid & 15) << 2;
        float4 v4 = *reinterpret_cast<const float4*>(&g_q[base_q + r * EE + d]);
        Qt[(d+0)*68 + r] = v4.x;
        Qt[(d+1)*68 + r] = v4.y;
        Qt[(d+2)*68 + r] = v4.z;
        Qt[(d+3)*68 + r] = v4.w;
    }
    if (tid < 64) { m_sm[tid] = -3.0e38f; l_sm[tid] = 0.f; }

    float o[4][4] = {};

    for (int kt = 0; kt <= qt; kt++) {
        __syncthreads();
        const int base_k = (b * TT + kt * 64) * EE + h * DH;
        #pragma unroll
        for (int rep = 0; rep < 4; rep++) {
            int r = (tid >> 4) + rep * 16;
            int d = (tid & 15) << 2;
            float4 k4 = *reinterpret_cast<const float4*>(&g_k[base_k + r * EE + d]);
            KtP[(d+0)*68 + r] = k4.x;
            KtP[(d+1)*68 + r] = k4.y;
            KtP[(d+2)*68 + r] = k4.z;
            KtP[(d+3)*68 + r] = k4.w;
            float4 v4 = *reinterpret_cast<const float4*>(&g_v[base_k + r * EE + d]);
            *reinterpret_cast<float4*>(&Vs[r*68 + d]) = v4;
        }
        __syncthreads();

        float s[4][4] = {};
        #pragma unroll 8
        for (int d = 0; d < 64; d++) {
            float4 a4 = *reinterpret_cast<const float4*>(&Qt [d*68 + (ty << 2)]);
            float4 b4 = *reinterpret_cast<const float4*>(&KtP[d*68 + (tx << 2)]);
            float av[4] = {a4.x, a4.y, a4.z, a4.w};
            float bv[4] = {b4.x, b4.y, b4.z, b4.w};
            #pragma unroll
            for (int i = 0; i < 4; i++)
                #pragma unroll
                for (int j = 0; j < 4; j++)
                    s[i][j] = fmaf(av[i], bv[j], s[i][j]);
        }

        const bool diag = (kt == qt);
        #pragma unroll
        for (int i = 0; i < 4; i++) {
            float rm = -3.0e38f;
            #pragma unroll
            for (int j = 0; j < 4; j++) {
                float sv = s[i][j] * scale;
                if (diag && ((tx << 2) + j) > ((ty << 2) + i)) sv = -1.0e30f;
                s[i][j] = sv;
                rm = fmaxf(rm, sv);
            }
            red[((ty << 2) + i) * 16 + tx] = rm;
        }
        __syncthreads();

        if (tid < 64) {
            float mt = red[tid * 16];
            #pragma unroll
            for (int u = 1; u < 16; u++) mt = fmaxf(mt, red[tid * 16 + u]);
            float mn = fmaxf(m_sm[tid], mt);
            c_sm[tid] = __expf(m_sm[tid] - mn);
            m_sm[tid] = mn;
        }
        __syncthreads();

        #pragma unroll
        for (int i = 0; i < 4; i++) {
            int r = (ty << 2) + i;
            float mn = m_sm[r];
            float cr = c_sm[r];
            float rs = 0.f;
            float pv[4];
            #pragma unroll
            for (int j = 0; j < 4; j++) {
                float pval = __expf(s[i][j] - mn);
                pv[j] = pval;
                rs += pval;
                o[i][j] *= cr;
            }
            float4 p4; p4.x = pv[0]; p4.y = pv[1]; p4.z = pv[2]; p4.w = pv[3];
            *reinterpret_cast<float4*>(&KtP[r*68 + (tx << 2)]) = p4;
            red[r * 16 + tx] = rs;
        }
        __syncthreads();

        if (tid < 64) {
            float rs = 0.f;
            #pragma unroll
            for (int u = 0; u < 16; u++) rs += red[tid * 16 + u];
            l_sm[tid] = l_sm[tid] * c_sm[tid] + rs;
        }

        #pragma unroll 8
        for (int k = 0; k < 64; k++) {
            float av[4];
            av[0] = KtP[((ty << 2) + 0) * 68 + k];
            av[1] = KtP[((ty << 2) + 1) * 68 + k];
            av[2] = KtP[((ty << 2) + 2) * 68 + k];
            av[3] = KtP[((ty << 2) + 3) * 68 + k];
            float4 b4 = *reinterpret_cast<const float4*>(&Vs[k*68 + (tx << 2)]);
            float bv[4] = {b4.x, b4.y, b4.z, b4.w};
            #pragma unroll
            for (int i = 0; i < 4; i++)
                #pragma unroll
                for (int j = 0; j < 4; j++)
                    o[i][j] = fmaf(av[i], bv[j], o[i][j]);
        }
    }
    __syncthreads();

    #pragma unroll
    for (int i = 0; i < 4; i++) {
        int r = (ty << 2) + i;
        float inv_l = 1.f / l_sm[r];
        #pragma unroll
        for (int j = 0; j < 4; j++) {
            int cc = (tx << 2) + j;
            int idx = base_q + r * EE + cc;
            g_x1[idx] = x[idx] + o[i][j] * inv_l;
        }
    }
}

// ---------------------------------------------------------------------------
extern "C" void kernel_launch(void* const* d_in, const int* in_sizes, int n_in,
                              void* d_out, int out_size)
{
    const float* x  = (const float*)d_in[0];
    const float* Wq = (const float*)d_in[1];
    const float* Wk = (const float*)d_in[2];
    const float* Wv = (const float*)d_in[3];
    const float* Wf = (const float*)d_in[4];
    const float* bf = (const float*)d_in[5];
    float* out = (float*)d_out;

    float *gq, *gk, *gv, *gx1;
    cudaGetSymbolAddress((void**)&gq,  g_q);
    cudaGetSymbolAddress((void**)&gk,  g_k);
    cudaGetSymbolAddress((void**)&gv,  g_v);
    cudaGetSymbolAddress((void**)&gx1, g_x1);

    cudaFuncSetAttribute(gemm_tc<0>, cudaFuncAttributeMaxDynamicSharedMemorySize, GEMM_SMEM);
    cudaFuncSetAttribute(gemm_tc<1>, cudaFuncAttributeMaxDynamicSharedMemorySize, GEMM_SMEM);

    dim3 gg(EE / 256, MM / 128);   // (4, 32) = 128 CTAs, one wave
    gemm_tc<0><<<gg, 256, GEMM_SMEM>>>(x,   Wq, gq, nullptr);
    gemm_tc<0><<<gg, 256, GEMM_SMEM>>>(x,   Wk, gk, nullptr);
    gemm_tc<0><<<gg, 256, GEMM_SMEM>>>(x,   Wv, gv, nullptr);

    const int attn_smem = (3 * 64 * 68 + 64 * 16 + 3 * 64) * (int)sizeof(float);
    cudaFuncSetAttribute(attn_kernel, cudaFuncAttributeMaxDynamicSharedMemorySize, attn_smem);
    attn_kernel<<<dim3(TT / 64, BB * HH), 256, attn_smem>>>(x);

    gemm_tc<1><<<gg, 256, GEMM_SMEM>>>(gx1, Wf, out, bf);
}

// round 5
// speedup vs baseline: 6.9070x; 2.3933x over previous
#include <cuda_runtime.h>
#include <cuda_bf16.h>
#include <cstdint>
#include <math.h>

#define BB 2
#define TT 2048
#define EE 1024
#define HH 16
#define DH 64
#define MM (BB*TT)   // 4096

// Scratch (__device__ globals; allocations are forbidden)
__device__ float g_q [MM*EE];
__device__ float g_k [MM*EE];
__device__ float g_v [MM*EE];
__device__ float g_x1[MM*EE];

// ---------------------------------------------------------------------------
// Baseline-PTX helpers (sm_80-era: mma.sync + cp.async; tcgen05 is rejected
// by this toolchain's compute_103 PTX target).
// ---------------------------------------------------------------------------
__device__ __forceinline__ uint32_t smem_u32(const void* p){
    uint32_t a;
    asm("{ .reg .u64 t; cvta.to.shared.u64 t, %1; cvt.u32.u64 %0, t; }":"=r"(a):"l"(p));
    return a;
}
#define CP16(dst,src)  asm volatile("cp.async.cg.shared.global [%0], [%1], 16;\n"::"r"(dst),"l"(src))
#define CP_COMMIT()    asm volatile("cp.async.commit_group;\n":::"memory")
#define CP_WAIT1()     asm volatile("cp.async.wait_group 1;\n":::"memory")
#define CP_WAIT0()     asm volatile("cp.async.wait_group 0;\n":::"memory")

__device__ __forceinline__ void mma_tf32(float c[4], uint32_t a0, uint32_t a1,
                                         uint32_t a2, uint32_t a3,
                                         uint32_t b0, uint32_t b1){
    asm volatile(
        "mma.sync.aligned.m16n8k8.row.col.f32.tf32.tf32.f32 "
        "{%0,%1,%2,%3}, {%4,%5,%6,%7}, {%8,%9}, {%0,%1,%2,%3};\n"
        : "+f"(c[0]), "+f"(c[1]), "+f"(c[2]), "+f"(c[3])
        : "r"(a0), "r"(a1), "r"(a2), "r"(a3), "r"(b0), "r"(b1));
}
__device__ __forceinline__ void mma_bf16(float c[4], uint32_t a0, uint32_t a1,
                                         uint32_t a2, uint32_t a3,
                                         uint32_t b0, uint32_t b1){
    asm volatile(
        "mma.sync.aligned.m16n8k16.row.col.f32.bf16.bf16.f32 "
        "{%0,%1,%2,%3}, {%4,%5,%6,%7}, {%8,%9}, {%0,%1,%2,%3};\n"
        : "+f"(c[0]), "+f"(c[1]), "+f"(c[2]), "+f"(c[3])
        : "r"(a0), "r"(a1), "r"(a2), "r"(a3), "r"(b0), "r"(b1));
}
__device__ __forceinline__ float ex2f(float x){
    float y; asm("ex2.approx.f32 %0, %1;":"=f"(y):"f"(x)); return y;
}

// ---------------------------------------------------------------------------
// tf32 mma.sync GEMM (proven R4): CTA 128x256, BK=32, 8 warps, warp 64x64.
// QKV==1: fused 3-projection variant (blockIdx.x selects Wq/Wk/Wv + dest).
// EPI==1: C = A + relu(acc + bias).
// ---------------------------------------------------------------------------
#define A_ST 36
#define B_ST 264
#define A_TILE (128*A_ST)
#define B_TILE (32*B_ST)
#define STAGE  (A_TILE + B_TILE)
#define GEMM_SMEM (2*STAGE*4)        // 104448 bytes

template<int EPI, int QKV>
__global__ void __launch_bounds__(256) gemm_tc(const float* __restrict__ A,
                                               const float* __restrict__ W0,
                                               const float* __restrict__ W1,
                                               const float* __restrict__ W2,
                                               float* __restrict__ C0,
                                               float* __restrict__ C1,
                                               float* __restrict__ C2,
                                               const float* __restrict__ bias)
{
    extern __shared__ float sm[];
    const uint32_t sbase = smem_u32(sm);
    const int tid  = threadIdx.x;
    const int wid  = tid >> 5, lane = tid & 31;
    const int ty   = lane >> 2, tx = lane & 3;
    const int wm   = wid >> 2;
    const int wn   = wid & 3;
    const int row0 = blockIdx.y * 128;
    const float* W;
    float* C;
    int col0;
    if (QKV) {
        int sel = blockIdx.x >> 2;
        W = (sel == 0) ? W0 : (sel == 1) ? W1 : W2;
        C = (sel == 0) ? C0 : (sel == 1) ? C1 : C2;
        col0 = (blockIdx.x & 3) * 256;
    } else {
        W = W0; C = C0; col0 = blockIdx.x * 256;
    }

    float c[4][8][4];
    #pragma unroll
    for (int mf = 0; mf < 4; mf++)
        #pragma unroll
        for (int nf = 0; nf < 8; nf++)
            #pragma unroll
            for (int u = 0; u < 4; u++) c[mf][nf][u] = 0.f;

    auto load_tiles = [&](int st, int k0){
        uint32_t sA = sbase + st * (STAGE * 4);
        uint32_t sB = sA + A_TILE * 4;
        #pragma unroll
        for (int t = 0; t < 4; t++) {
            int s  = tid + t * 256;
            int r  = s >> 3;
            int cf = (s & 7) << 2;
            CP16(sA + (uint32_t)(r * A_ST + cf) * 4,
                 A + (size_t)(row0 + r) * EE + k0 + cf);
        }
        #pragma unroll
        for (int t = 0; t < 8; t++) {
            int s  = tid + t * 256;
            int r  = s >> 6;
            int cf = (s & 63) << 2;
            CP16(sB + (uint32_t)(r * B_ST + cf) * 4,
                 W + (size_t)(k0 + r) * EE + col0 + cf);
        }
    };

    load_tiles(0, 0);
    CP_COMMIT();

    for (int kt = 0; kt < 32; kt++) {
        const int b = kt & 1;
        if (kt + 1 < 32) {
            load_tiles(1 - b, (kt + 1) << 5);
            CP_COMMIT();
            CP_WAIT1();
        } else {
            CP_WAIT0();
        }
        __syncthreads();

        const float* As = sm + b * STAGE;
        const float* Bs = As + A_TILE;

        #pragma unroll
        for (int ks = 0; ks < 4; ks++) {
            const int k = ks << 3;
            uint32_t a[4][4];
            #pragma unroll
            for (int mf = 0; mf < 4; mf++) {
                const int rb = wm * 64 + mf * 16;
                a[mf][0] = __float_as_uint(As[(rb + ty    ) * A_ST + k + tx    ]);
                a[mf][1] = __float_as_uint(As[(rb + ty + 8) * A_ST + k + tx    ]);
                a[mf][2] = __float_as_uint(As[(rb + ty    ) * A_ST + k + tx + 4]);
                a[mf][3] = __float_as_uint(As[(rb + ty + 8) * A_ST + k + tx + 4]);
            }
            uint32_t bfr[8][2];
            #pragma unroll
            for (int nf = 0; nf < 8; nf++) {
                const int n = wn * 64 + nf * 8 + ty;
                bfr[nf][0] = __float_as_uint(Bs[(k + tx    ) * B_ST + n]);
                bfr[nf][1] = __float_as_uint(Bs[(k + tx + 4) * B_ST + n]);
            }
            #pragma unroll
            for (int mf = 0; mf < 4; mf++)
                #pragma unroll
                for (int nf = 0; nf < 8; nf++)
                    mma_tf32(c[mf][nf], a[mf][0], a[mf][1], a[mf][2], a[mf][3],
                             bfr[nf][0], bfr[nf][1]);
        }
        __syncthreads();
    }

    #pragma unroll
    for (int mf = 0; mf < 4; mf++) {
        const int r = row0 + wm * 64 + mf * 16 + ty;
        #pragma unroll
        for (int nf = 0; nf < 8; nf++) {
            const int cc = col0 + wn * 64 + nf * 8 + (tx << 1);
            float2 v0 = make_float2(c[mf][nf][0], c[mf][nf][1]);
            float2 v1 = make_float2(c[mf][nf][2], c[mf][nf][3]);
            if (EPI == 1) {
                float2 bb = *reinterpret_cast<const float2*>(bias + cc);
                float2 x0 = *reinterpret_cast<const float2*>(A + (size_t)r * EE + cc);
                float2 x1 = *reinterpret_cast<const float2*>(A + (size_t)(r + 8) * EE + cc);
                v0.x = x0.x + fmaxf(v0.x + bb.x, 0.f);
                v0.y = x0.y + fmaxf(v0.y + bb.y, 0.f);
                v1.x = x1.x + fmaxf(v1.x + bb.x, 0.f);
                v1.y = x1.y + fmaxf(v1.y + bb.y, 0.f);
            }
            *reinterpret_cast<float2*>(C + (size_t)r * EE + cc) = v0;
            *reinterpret_cast<float2*>(C + (size_t)(r + 8) * EE + cc) = v1;
        }
    }
}

// ---------------------------------------------------------------------------
// Tensor-core flash attention (causal, online softmax).
// CTA: 128 q-rows x one (b,h). 8 warps x 16 q-rows. K-tile = 64.
// S via tf32 m16n8k8 (Q frags in regs, K smem stride 68 = conflict-free).
// Softmax in registers (ex2.approx, log2e folded into 1/sqrt(E) scale).
// P.V via bf16 m16n8k16 (accumulator->A-frag layout identity, V transposed
// bf16 in smem, stride 72 halves = conflict-free).
// Epilogue fuses residual: g_x1 = x + attn.
// ---------------------------------------------------------------------------
#define QT 128
#define KT 64
#define KST 68
#define VTST 72
// smem: KS[2][64][68] f32 | VST[2][64][64] f32 | VT[64][72] bf16
#define ATTN_SMEM ((2*64*KST + 2*64*64)*4 + 64*VTST*2)   // 76800 B

__global__ void __launch_bounds__(256, 1) attn_tc(const float* __restrict__ x)
{
    extern __shared__ float sm[];
    float* KS  = sm;                       // [2][64][68]
    float* VST = sm + 2*64*KST;            // [2][64][64]
    __nv_bfloat16* VT = (__nv_bfloat16*)(VST + 2*64*64);   // [64][72]
    const uint32_t sb_KS  = smem_u32(KS);
    const uint32_t sb_VST = smem_u32(VST);

    const int tid = threadIdx.x;
    const int wid = tid >> 5, lane = tid & 31;
    const int ty = lane >> 2, tx = lane & 3;
    const int bh = blockIdx.y, b = bh >> 4, h = bh & 15;
    const int qb = blockIdx.x * QT;
    const int ktmax = (qb + QT - 1) >> 6;          // >= 1 always
    const float sc2 = 0.03125f * 1.44269504088896f;  // 1/sqrt(1024) * log2(e)

    // ---- stage Q through KS, build A-fragments ----
    #pragma unroll
    for (int t = 0; t < 8; t++) {
        int s = tid + t * 256;
        int r = s >> 4;               // 0..127
        int c4 = (s & 15) << 2;       // 0..60
        CP16(sb_KS + (uint32_t)(r * KST + c4) * 4,
             g_q + (size_t)(b * TT + qb + r) * EE + h * DH + c4);
    }
    CP_COMMIT(); CP_WAIT0();
    __syncthreads();

    uint32_t qa[8][4];
    {
        const float* Qw = KS + (wid * 16) * KST;
        #pragma unroll
        for (int kf = 0; kf < 8; kf++) {
            int k = kf * 8;
            qa[kf][0] = __float_as_uint(Qw[(ty    ) * KST + k + tx    ]);
            qa[kf][1] = __float_as_uint(Qw[(ty + 8) * KST + k + tx    ]);
            qa[kf][2] = __float_as_uint(Qw[(ty    ) * KST + k + tx + 4]);
            qa[kf][3] = __float_as_uint(Qw[(ty + 8) * KST + k + tx + 4]);
        }
    }
    __syncthreads();

    float mrow[2] = {-1e30f, -1e30f};
    float lrow[2] = {0.f, 0.f};
    float o[8][4];
    #pragma unroll
    for (int df = 0; df < 8; df++)
        #pragma unroll
        for (int u = 0; u < 4; u++) o[df][u] = 0.f;

    auto issue_tile = [&](int kt){
        const float* Kg = g_k + (size_t)(b * TT + kt * KT) * EE + h * DH;
        const float* Vg = g_v + (size_t)(b * TT + kt * KT) * EE + h * DH;
        uint32_t dK = sb_KS  + (uint32_t)((kt & 1) * 64 * KST) * 4;
        uint32_t dV = sb_VST + (uint32_t)((kt & 1) * 64 * 64) * 4;
        #pragma unroll
        for (int t = 0; t < 4; t++) {
            int s = tid + t * 256;
            int r = s >> 4; int c4 = (s & 15) << 2;
            CP16(dK + (uint32_t)(r * KST + c4) * 4, Kg + (size_t)r * EE + c4);
        }
        #pragma unroll
        for (int t = 0; t < 4; t++) {
            int s = tid + t * 256;
            int r = s >> 4; int c4 = (s & 15) << 2;
            CP16(dV + (uint32_t)(r * 64 + c4) * 4, Vg + (size_t)r * EE + c4);
        }
        CP_COMMIT();
    };

    issue_tile(0);
    issue_tile(1);

    for (int kt = 0; kt <= ktmax; kt++) {
        const int bs = kt & 1;
        if (kt < ktmax) { CP_WAIT1(); } else { CP_WAIT0(); }
        __syncthreads();

        // convert VST[bs] -> VT (bf16, transposed [d][kk])
        {
            const float* vs = VST + bs * 64 * 64;
            int d = tid & 63, kk0 = (tid >> 6) << 4;
            #pragma unroll
            for (int j = 0; j < 8; j++) {
                float v0 = vs[(kk0 + 2*j    ) * 64 + d];
                float v1 = vs[(kk0 + 2*j + 1) * 64 + d];
                __nv_bfloat162 p = __floats2bfloat162_rn(v0, v1);
                *reinterpret_cast<__nv_bfloat162*>(&VT[d * VTST + kk0 + 2*j]) = p;
            }
        }
        __syncthreads();

        // S = Q K^T
        float s[8][4];
        #pragma unroll
        for (int nf = 0; nf < 8; nf++)
            #pragma unroll
            for (int u = 0; u < 4; u++) s[nf][u] = 0.f;
        {
            const float* Kb = KS + bs * 64 * KST;
            #pragma unroll
            for (int kf = 0; kf < 8; kf++) {
                int k = kf * 8;
                uint32_t bk[8][2];
                #pragma unroll
                for (int nf = 0; nf < 8; nf++) {
                    int n = nf * 8 + ty;
                    bk[nf][0] = __float_as_uint(Kb[n * KST + k + tx    ]);
                    bk[nf][1] = __float_as_uint(Kb[n * KST + k + tx + 4]);
                }
                #pragma unroll
                for (int nf = 0; nf < 8; nf++)
                    mma_tf32(s[nf], qa[kf][0], qa[kf][1], qa[kf][2], qa[kf][3],
                             bk[nf][0], bk[nf][1]);
            }
        }

        // scale + causal mask + row max
        const int q0 = qb + wid * 16;
        const bool need_mask = (kt * KT + KT - 1) > q0;
        float pmax[2] = {-1e30f, -1e30f};
        #pragma unroll
        for (int nf = 0; nf < 8; nf++) {
            int kkb = kt * KT + nf * 8 + 2 * tx;
            #pragma unroll
            for (int u = 0; u < 4; u++) {
                float v = s[nf][u] * sc2;
                if (need_mask) {
                    int kkg = kkb + (u & 1);
                    int qg  = q0 + ty + ((u >> 1) << 3);
                    if (kkg > qg) v = -1e30f;
                }
                s[nf][u] = v;
                pmax[u >> 1] = fmaxf(pmax[u >> 1], v);
            }
        }
        #pragma unroll
        for (int r = 0; r < 2; r++) {
            pmax[r] = fmaxf(pmax[r], __shfl_xor_sync(0xffffffffu, pmax[r], 1));
            pmax[r] = fmaxf(pmax[r], __shfl_xor_sync(0xffffffffu, pmax[r], 2));
        }
        float mn0 = fmaxf(mrow[0], pmax[0]);
        float mn1 = fmaxf(mrow[1], pmax[1]);
        float cr0 = ex2f(mrow[0] - mn0);
        float cr1 = ex2f(mrow[1] - mn1);
        mrow[0] = mn0; mrow[1] = mn1;

        // P = 2^(s-m): pack bf16 A-frags, accumulate row sums
        uint32_t pa[4][4];
        float ls[2] = {0.f, 0.f};
        #pragma unroll
        for (int nf = 0; nf < 8; nf++) {
            float p0 = ex2f(s[nf][0] - mn0);
            float p1 = ex2f(s[nf][1] - mn0);
            float p2 = ex2f(s[nf][2] - mn1);
            float p3 = ex2f(s[nf][3] - mn1);
            ls[0] += p0 + p1;
            ls[1] += p2 + p3;
            uint32_t lo, hi;
            {
                __nv_bfloat162 t0 = __floats2bfloat162_rn(p0, p1);
                __nv_bfloat162 t1 = __floats2bfloat162_rn(p2, p3);
                lo = *reinterpret_cast<uint32_t*>(&t0);
                hi = *reinterpret_cast<uint32_t*>(&t1);
            }
            int kb = nf >> 1;
            if ((nf & 1) == 0) { pa[kb][0] = lo; pa[kb][1] = hi; }
            else               { pa[kb][2] = lo; pa[kb][3] = hi; }
        }
        #pragma unroll
        for (int r = 0; r < 2; r++) {
            ls[r] += __shfl_xor_sync(0xffffffffu, ls[r], 1);
            ls[r] += __shfl_xor_sync(0xffffffffu, ls[r], 2);
        }
        lrow[0] = lrow[0] * cr0 + ls[0];
        lrow[1] = lrow[1] * cr1 + ls[1];

        // rescale O, then O += P @ V
        #pragma unroll
        for (int df = 0; df < 8; df++) {
            o[df][0] *= cr0; o[df][1] *= cr0;
            o[df][2] *= cr1; o[df][3] *= cr1;
        }
        #pragma unroll
        for (int kb = 0; kb < 4; kb++) {
            #pragma unroll
            for (int df = 0; df < 8; df++) {
                int n = df * 8 + ty;
                uint32_t b0 = *reinterpret_cast<const uint32_t*>(&VT[n * VTST + kb * 16 + 2 * tx    ]);
                uint32_t b1 = *reinterpret_cast<const uint32_t*>(&VT[n * VTST + kb * 16 + 2 * tx + 8]);
                mma_bf16(o[df], pa[kb][0], pa[kb][1], pa[kb][2], pa[kb][3], b0, b1);
            }
        }
        __syncthreads();
        if (kt + 2 <= ktmax) issue_tile(kt + 2);
    }

    // epilogue: normalize + residual
    const float inv0 = 1.f / lrow[0];
    const float inv1 = 1.f / lrow[1];
    const size_t base = (size_t)(b * TT + qb + wid * 16) * EE + h * DH;
    #pragma unroll
    for (int df = 0; df < 8; df++) {
        int col = df * 8 + 2 * tx;
        {
            size_t idx = base + (size_t)ty * EE + col;
            float2 xv = *reinterpret_cast<const float2*>(&x[idx]);
            float2 ov = make_float2(xv.x + o[df][0] * inv0, xv.y + o[df][1] * inv0);
            *reinterpret_cast<float2*>(&g_x1[idx]) = ov;
        }
        {
            size_t idx = base + (size_t)(ty + 8) * EE + col;
            float2 xv = *reinterpret_cast<const float2*>(&x[idx]);
            float2 ov = make_float2(xv.x + o[df][2] * inv1, xv.y + o[df][3] * inv1);
            *reinterpret_cast<float2*>(&g_x1[idx]) = ov;
        }
    }
}

// ---------------------------------------------------------------------------
extern "C" void kernel_launch(void* const* d_in, const int* in_sizes, int n_in,
                              void* d_out, int out_size)
{
    const float* x  = (const float*)d_in[0];
    const float* Wq = (const float*)d_in[1];
    const float* Wk = (const float*)d_in[2];
    const float* Wv = (const float*)d_in[3];
    const float* Wf = (const float*)d_in[4];
    const float* bf = (const float*)d_in[5];
    float* out = (float*)d_out;

    float *gq, *gk, *gv, *gx1;
    cudaGetSymbolAddress((void**)&gq,  g_q);
    cudaGetSymbolAddress((void**)&gk,  g_k);
    cudaGetSymbolAddress((void**)&gv,  g_v);
    cudaGetSymbolAddress((void**)&gx1, g_x1);

    cudaFuncSetAttribute((const void*)gemm_tc<0,1>, cudaFuncAttributeMaxDynamicSharedMemorySize, GEMM_SMEM);
    cudaFuncSetAttribute((const void*)gemm_tc<1,0>, cudaFuncAttributeMaxDynamicSharedMemorySize, GEMM_SMEM);
    cudaFuncSetAttribute((const void*)attn_tc,      cudaFuncAttributeMaxDynamicSharedMemorySize, ATTN_SMEM);

    // fused QKV projections: 12 x 32 = 384 CTAs
    gemm_tc<0,1><<<dim3(12, MM/128), 256, GEMM_SMEM>>>(x, Wq, Wk, Wv, gq, gk, gv, nullptr);

    // tensor-core flash attention + residual
    attn_tc<<<dim3(TT/QT, BB*HH), 256, ATTN_SMEM>>>(x);

    // FFN + bias + relu + residual
    gemm_tc<1,0><<<dim3(4, MM/128), 256, GEMM_SMEM>>>(gx1, Wf, nullptr, nullptr, out, nullptr, nullptr, bf);
}

// round 11
// speedup vs baseline: 9.0267x; 1.3069x over previous
#include <cuda_runtime.h>
#include <cuda_bf16.h>
#include <cstdint>
#include <math.h>

#define BB 2
#define TT 2048
#define EE 1024
#define HH 16
#define DH 64
#define MM (BB*TT)   // 4096

// Scratch (__device__ globals; allocations are forbidden)
__device__ float          g_x1[MM*EE];          // attn+residual output (f32, FFN input)
__device__ __nv_bfloat16  g_xh[MM*EE];          // x in bf16 (QKV A operand)
__device__ __nv_bfloat16  g_qh[MM*EE];
__device__ __nv_bfloat16  g_kh[MM*EE];
__device__ __nv_bfloat16  g_vh[MM*EE];
__device__ __nv_bfloat16  g_wth[3][EE*EE];      // Wq,Wk,Wv transposed [n][k] bf16

// ---------------------------------------------------------------------------
// Baseline-PTX helpers (sm_80-era: mma.sync + cp.async + ldmatrix).
// ---------------------------------------------------------------------------
__device__ __forceinline__ uint32_t smem_u32(const void* p){
    uint32_t a;
    asm("{ .reg .u64 t; cvta.to.shared.u64 t, %1; cvt.u32.u64 %0, t; }":"=r"(a):"l"(p));
    return a;
}
#define CP16(dst,src)  asm volatile("cp.async.cg.shared.global [%0], [%1], 16;\n"::"r"(dst),"l"(src))
#define CP_COMMIT()    asm volatile("cp.async.commit_group;\n":::"memory")
#define CP_WAIT1()     asm volatile("cp.async.wait_group 1;\n":::"memory")
#define CP_WAIT0()     asm volatile("cp.async.wait_group 0;\n":::"memory")
#define LDSM4(r0,r1,r2,r3,addr) \
    asm volatile("ldmatrix.sync.aligned.m8n8.x4.shared.b16 {%0,%1,%2,%3}, [%4];" \
        :"=r"(r0),"=r"(r1),"=r"(r2),"=r"(r3):"r"(addr))
#define LDSM4T(r0,r1,r2,r3,addr) \
    asm volatile("ldmatrix.sync.aligned.m8n8.x4.trans.shared.b16 {%0,%1,%2,%3}, [%4];" \
        :"=r"(r0),"=r"(r1),"=r"(r2),"=r"(r3):"r"(addr))

__device__ __forceinline__ void mma_tf32(float c[4], uint32_t a0, uint32_t a1,
                                         uint32_t a2, uint32_t a3,
                                         uint32_t b0, uint32_t b1){
    asm volatile(
        "mma.sync.aligned.m16n8k8.row.col.f32.tf32.tf32.f32 "
        "{%0,%1,%2,%3}, {%4,%5,%6,%7}, {%8,%9}, {%0,%1,%2,%3};\n"
        : "+f"(c[0]), "+f"(c[1]), "+f"(c[2]), "+f"(c[3])
        : "r"(a0), "r"(a1), "r"(a2), "r"(a3), "r"(b0), "r"(b1));
}
__device__ __forceinline__ void mma_bf16(float c[4], uint32_t a0, uint32_t a1,
                                         uint32_t a2, uint32_t a3,
                                         uint32_t b0, uint32_t b1){
    asm volatile(
        "mma.sync.aligned.m16n8k16.row.col.f32.bf16.bf16.f32 "
        "{%0,%1,%2,%3}, {%4,%5,%6,%7}, {%8,%9}, {%0,%1,%2,%3};\n"
        : "+f"(c[0]), "+f"(c[1]), "+f"(c[2]), "+f"(c[3])
        : "r"(a0), "r"(a1), "r"(a2), "r"(a3), "r"(b0), "r"(b1));
}
__device__ __forceinline__ float ex2f(float x){
    float y; asm("ex2.approx.f32 %0, %1;":"=f"(y):"f"(x)); return y;
}

// ---------------------------------------------------------------------------
// Prologue: x -> bf16, and Wq/Wk/Wv -> transposed bf16 [n][k]
// ---------------------------------------------------------------------------
__global__ void __launch_bounds__(256) cvt_x_kernel(const float* __restrict__ x)
{
    int i = (blockIdx.x * 256 + threadIdx.x) * 4;
    float4 v = *reinterpret_cast<const float4*>(x + i);
    __nv_bfloat162 p0 = __floats2bfloat162_rn(v.x, v.y);
    __nv_bfloat162 p1 = __floats2bfloat162_rn(v.z, v.w);
    uint2 u;
    u.x = *reinterpret_cast<uint32_t*>(&p0);
    u.y = *reinterpret_cast<uint32_t*>(&p1);
    *reinterpret_cast<uint2*>(&g_xh[i]) = u;
}

__global__ void __launch_bounds__(256) tpose_bf_kernel(const float* __restrict__ W, int slot)
{
    __shared__ float t[32][33];
    int x  = blockIdx.x * 32 + threadIdx.x;   // n
    int y0 = blockIdx.y * 32;                 // k
    #pragma unroll
    for (int dy = threadIdx.y; dy < 32; dy += 8)
        t[dy][threadIdx.x] = W[(size_t)(y0 + dy) * EE + x];
    __syncthreads();
    __nv_bfloat16* out = g_wth[slot];
    int ko = y0 + threadIdx.x;
    int n0 = blockIdx.x * 32;
    #pragma unroll
    for (int dy = threadIdx.y; dy < 32; dy += 8)
        out[(size_t)(n0 + dy) * EE + ko] = __float2bfloat16(t[threadIdx.x][dy]);
}

// ---------------------------------------------------------------------------
// bf16 QKV GEMM (fused 3 projections): C = x @ W  via all-ldmatrix fragments.
// CTA 128x256, BK=32, 8 warps (2m x 4n), warp 64x64. A = g_xh [m][k] bf16,
// B = g_wth[sel] [n][k] bf16. Smem rows padded to 80B (conflict-free LDSM).
// Outputs bf16 to g_qh/g_kh/g_vh.
// ---------------------------------------------------------------------------
#define HST 40                     // halfwords per smem row (32 data + 8 pad)
#define HA_BYTES (128*HST*2)       // 10240
#define HB_BYTES (256*HST*2)       // 20480
#define HSTAGE   (HA_BYTES + HB_BYTES)   // 30720
#define QKV_SMEM (2*HSTAGE)        // 61440

__global__ void __launch_bounds__(256) qkv_gemm()
{
    extern __shared__ char smc[];
    const uint32_t sbase = smem_u32(smc);
    const int tid  = threadIdx.x;
    const int wid  = tid >> 5, lane = tid & 31;
    const int ty   = lane >> 2, tx = lane & 3;
    const int wm   = wid >> 2;
    const int wn   = wid & 3;
    const int row0 = blockIdx.y * 128;
    const int sel  = blockIdx.x >> 2;
    const int col0 = (blockIdx.x & 3) * 256;
    const __nv_bfloat16* Wt = g_wth[sel];
    __nv_bfloat16* C = (sel == 0) ? g_qh : (sel == 1) ? g_kh : g_vh;

    float c[4][8][4];
    #pragma unroll
    for (int mf = 0; mf < 4; mf++)
        #pragma unroll
        for (int nf = 0; nf < 8; nf++)
            #pragma unroll
            for (int u = 0; u < 4; u++) c[mf][nf][u] = 0.f;

    auto load_tiles = [&](int st, int k0){
        uint32_t sA = sbase + st * HSTAGE;
        uint32_t sB = sA + HA_BYTES;
        #pragma unroll
        for (int t = 0; t < 2; t++) {               // A: 128 rows x 4 chunks (32 bf16 = 64B)
            int s = tid + t * 256;
            int r = s >> 2, ch = s & 3;
            CP16(sA + (uint32_t)(r * 80 + ch * 16),
                 g_xh + (size_t)(row0 + r) * EE + k0 + ch * 8);
        }
        #pragma unroll
        for (int t = 0; t < 4; t++) {               // B: 256 rows x 4 chunks
            int s = tid + t * 256;
            int r = s >> 2, ch = s & 3;
            CP16(sB + (uint32_t)(r * 80 + ch * 16),
                 Wt + (size_t)(col0 + r) * EE + k0 + ch * 8);
        }
    };

    load_tiles(0, 0);
    CP_COMMIT();

    for (int kt = 0; kt < 32; kt++) {
        const int b = kt & 1;
        if (kt + 1 < 32) {
            load_tiles(1 - b, (kt + 1) << 5);
            CP_COMMIT();
            CP_WAIT1();
        } else {
            CP_WAIT0();
        }
        __syncthreads();

        const uint32_t sA = sbase + b * HSTAGE;
        const uint32_t sB = sA + HA_BYTES;

        #pragma unroll
        for (int ks = 0; ks < 2; ks++) {
            uint32_t a[4][4];
            #pragma unroll
            for (int mf = 0; mf < 4; mf++) {
                uint32_t row = wm * 64 + mf * 16 + (lane & 15);
                uint32_t kh  = ks * 16 + ((lane & 16) >> 1);
                LDSM4(a[mf][0], a[mf][1], a[mf][2], a[mf][3],
                      sA + row * 80 + kh * 2);
            }
            uint32_t bfr[8][2];
            #pragma unroll
            for (int p = 0; p < 4; p++) {
                uint32_t row = wn * 64 + p * 16 + (lane & 7) + ((lane & 16) >> 1);
                uint32_t kh  = ks * 16 + (lane & 8);
                LDSM4(bfr[2*p][0], bfr[2*p][1], bfr[2*p+1][0], bfr[2*p+1][1],
                      sB + row * 80 + kh * 2);
            }
            #pragma unroll
            for (int mf = 0; mf < 4; mf++)
                #pragma unroll
                for (int nf = 0; nf < 8; nf++)
                    mma_bf16(c[mf][nf], a[mf][0], a[mf][1], a[mf][2], a[mf][3],
                             bfr[nf][0], bfr[nf][1]);
        }
        __syncthreads();
    }

    #pragma unroll
    for (int mf = 0; mf < 4; mf++) {
        const int r = row0 + wm * 64 + mf * 16 + ty;
        #pragma unroll
        for (int nf = 0; nf < 8; nf++) {
            const int cc = col0 + wn * 64 + nf * 8 + (tx << 1);
            __nv_bfloat162 p0 = __floats2bfloat162_rn(c[mf][nf][0], c[mf][nf][1]);
            __nv_bfloat162 p1 = __floats2bfloat162_rn(c[mf][nf][2], c[mf][nf][3]);
            *reinterpret_cast<__nv_bfloat162*>(&C[(size_t)r * EE + cc]) = p0;
            *reinterpret_cast<__nv_bfloat162*>(&C[(size_t)(r + 8) * EE + cc]) = p1;
        }
    }
}

// ---------------------------------------------------------------------------
// bf16 flash attention (causal, online softmax), all-ldmatrix fragments.
// CTA: 128 q-rows x one (b,h). 8 warps x 16 q-rows. K-tile = 64.
// NOTE: rows are 64 bf16 = 128 BYTES = 8 x 16B chunks (R10 bug: staged only 4).
// Smem rows 72 halfwords (144B): 16B-aligned, distinct mod 128.
// Epilogue fuses residual: g_x1 = x + attn.
// ---------------------------------------------------------------------------
#define QT 128
#define AST 72                                  // halfwords per row
#define AT_BYTES (64*AST*2)                     // 9216 per stage
#define ATTN_SMEM (4*AT_BYTES)                  // 36864: KS[2] + VS[2]

__global__ void __launch_bounds__(256, 1) attn_tc(const float* __restrict__ x)
{
    extern __shared__ char smc[];
    const uint32_t sb_KS = smem_u32(smc);               // [2][64][72]h (Q staged here too)
    const uint32_t sb_VS = sb_KS + 2 * AT_BYTES;        // [2][64][72]h

    const int tid = threadIdx.x;
    const int wid = tid >> 5, lane = tid & 31;
    const int ty = lane >> 2, tx = lane & 3;
    const int bh = blockIdx.y, b = bh >> 4, h = bh & 15;
    const int qb = blockIdx.x * QT;
    const int ktmax = (qb + QT - 1) >> 6;
    const float sc2 = 0.03125f * 1.44269504088896f;     // 1/sqrt(1024) * log2e

    // ---- stage Q (128 rows x 8 chunks of 16B) through KS area ----
    {
        const __nv_bfloat16* Qg = g_qh + (size_t)(b * TT + qb) * EE + h * DH;
        #pragma unroll
        for (int t = 0; t < 4; t++) {
            int s = tid + t * 256;          // 0..1023
            int r = s >> 3, ch = s & 7;     // 128 rows x 8 chunks
            CP16(sb_KS + (uint32_t)(r * 144 + ch * 16), Qg + (size_t)r * EE + ch * 8);
        }
        CP_COMMIT(); CP_WAIT0();
    }
    __syncthreads();

    uint32_t qa[4][4];
    #pragma unroll
    for (int kf = 0; kf < 4; kf++) {
        uint32_t row = wid * 16 + (lane & 15);
        uint32_t kh  = kf * 16 + ((lane & 16) >> 1);
        LDSM4(qa[kf][0], qa[kf][1], qa[kf][2], qa[kf][3],
              sb_KS + row * 144 + kh * 2);
    }
    __syncthreads();

    float mrow[2] = {-1e30f, -1e30f};
    float lrow[2] = {0.f, 0.f};
    float o[8][4];
    #pragma unroll
    for (int df = 0; df < 8; df++)
        #pragma unroll
        for (int u = 0; u < 4; u++) o[df][u] = 0.f;

    auto issue_tile = [&](int kt){
        const __nv_bfloat16* Kg = g_kh + (size_t)(b * TT + kt * 64) * EE + h * DH;
        const __nv_bfloat16* Vg = g_vh + (size_t)(b * TT + kt * 64) * EE + h * DH;
        uint32_t dK = sb_KS + (uint32_t)((kt & 1) * AT_BYTES);
        uint32_t dV = sb_VS + (uint32_t)((kt & 1) * AT_BYTES);
        #pragma unroll
        for (int t = 0; t < 2; t++) {
            int s = tid + t * 256;          // 0..511
            int r = s >> 3, ch = s & 7;     // 64 rows x 8 chunks
            CP16(dK + (uint32_t)(r * 144 + ch * 16), Kg + (size_t)r * EE + ch * 8);
            CP16(dV + (uint32_t)(r * 144 + ch * 16), Vg + (size_t)r * EE + ch * 8);
        }
        CP_COMMIT();
    };

    issue_tile(0);
    issue_tile(1);

    for (int kt = 0; kt <= ktmax; kt++) {
        const int bs = kt & 1;
        if (kt < ktmax) { CP_WAIT1(); } else { CP_WAIT0(); }
        __syncthreads();

        const uint32_t sK = sb_KS + bs * AT_BYTES;
        const uint32_t sV = sb_VS + bs * AT_BYTES;

        // S = Q K^T (bf16 m16n8k16)
        float s[8][4];
        #pragma unroll
        for (int nf = 0; nf < 8; nf++)
            #pragma unroll
            for (int u = 0; u < 4; u++) s[nf][u] = 0.f;
        #pragma unroll
        for (int kf = 0; kf < 4; kf++) {
            uint32_t bk[8][2];
            #pragma unroll
            for (int p = 0; p < 4; p++) {
                uint32_t row = p * 16 + (lane & 7) + ((lane & 16) >> 1);
                uint32_t kh  = kf * 16 + (lane & 8);
                LDSM4(bk[2*p][0], bk[2*p][1], bk[2*p+1][0], bk[2*p+1][1],
                      sK + row * 144 + kh * 2);
            }
            #pragma unroll
            for (int nf = 0; nf < 8; nf++)
                mma_bf16(s[nf], qa[kf][0], qa[kf][1], qa[kf][2], qa[kf][3],
                         bk[nf][0], bk[nf][1]);
        }

        // scale + causal mask + row max
        const int q0 = qb + wid * 16;
        const bool need_mask = (kt * 64 + 63) > q0;
        float pmax[2] = {-1e30f, -1e30f};
        #pragma unroll
        for (int nf = 0; nf < 8; nf++) {
            int kkb = kt * 64 + nf * 8 + 2 * tx;
            #pragma unroll
            for (int u = 0; u < 4; u++) {
                float v = s[nf][u] * sc2;
                if (need_mask) {
                    int kkg = kkb + (u & 1);
                    int qg  = q0 + ty + ((u >> 1) << 3);
                    if (kkg > qg) v = -1e30f;
                }
                s[nf][u] = v;
                pmax[u >> 1] = fmaxf(pmax[u >> 1], v);
            }
        }
        #pragma unroll
        for (int r = 0; r < 2; r++) {
            pmax[r] = fmaxf(pmax[r], __shfl_xor_sync(0xffffffffu, pmax[r], 1));
            pmax[r] = fmaxf(pmax[r], __shfl_xor_sync(0xffffffffu, pmax[r], 2));
        }
        float mn0 = fmaxf(mrow[0], pmax[0]);
        float mn1 = fmaxf(mrow[1], pmax[1]);
        float cr0 = ex2f(mrow[0] - mn0);
        float cr1 = ex2f(mrow[1] - mn1);
        mrow[0] = mn0; mrow[1] = mn1;

        // P = 2^(s-m): pack bf16 A-frags + row sums
        uint32_t pa[4][4];
        float ls[2] = {0.f, 0.f};
        #pragma unroll
        for (int nf = 0; nf < 8; nf++) {
            float p0 = ex2f(s[nf][0] - mn0);
            float p1 = ex2f(s[nf][1] - mn0);
            float p2 = ex2f(s[nf][2] - mn1);
            float p3 = ex2f(s[nf][3] - mn1);
            ls[0] += p0 + p1;
            ls[1] += p2 + p3;
            __nv_bfloat162 t0 = __floats2bfloat162_rn(p0, p1);
            __nv_bfloat162 t1 = __floats2bfloat162_rn(p2, p3);
            uint32_t lo = *reinterpret_cast<uint32_t*>(&t0);
            uint32_t hi = *reinterpret_cast<uint32_t*>(&t1);
            int kb = nf >> 1;
            if ((nf & 1) == 0) { pa[kb][0] = lo; pa[kb][1] = hi; }
            else               { pa[kb][2] = lo; pa[kb][3] = hi; }
        }
        #pragma unroll
        for (int r = 0; r < 2; r++) {
            ls[r] += __shfl_xor_sync(0xffffffffu, ls[r], 1);
            ls[r] += __shfl_xor_sync(0xffffffffu, ls[r], 2);
        }
        lrow[0] = lrow[0] * cr0 + ls[0];
        lrow[1] = lrow[1] * cr1 + ls[1];

        // rescale O, then O += P @ V  (V via ldmatrix.trans)
        #pragma unroll
        for (int df = 0; df < 8; df++) {
            o[df][0] *= cr0; o[df][1] *= cr0;
            o[df][2] *= cr1; o[df][3] *= cr1;
        }
        #pragma unroll
        for (int kb = 0; kb < 4; kb++) {
            uint32_t vb[8][2];
            #pragma unroll
            for (int dp = 0; dp < 4; dp++) {
                uint32_t row = kb * 16 + (lane & 15);
                uint32_t dhh = dp * 16 + ((lane & 16) >> 1);
                LDSM4T(vb[2*dp][0], vb[2*dp][1], vb[2*dp+1][0], vb[2*dp+1][1],
                       sV + row * 144 + dhh * 2);
            }
            #pragma unroll
            for (int df = 0; df < 8; df++)
                mma_bf16(o[df], pa[kb][0], pa[kb][1], pa[kb][2], pa[kb][3],
                         vb[df][0], vb[df][1]);
        }
        __syncthreads();
        if (kt + 2 <= ktmax) issue_tile(kt + 2);
    }

    // epilogue: normalize + residual
    const float inv0 = 1.f / lrow[0];
    const float inv1 = 1.f / lrow[1];
    const size_t base = (size_t)(b * TT + qb + wid * 16) * EE + h * DH;
    #pragma unroll
    for (int df = 0; df < 8; df++) {
        int col = df * 8 + 2 * tx;
        {
            size_t idx = base + (size_t)ty * EE + col;
            float2 xv = *reinterpret_cast<const float2*>(&x[idx]);
            float2 ov = make_float2(xv.x + o[df][0] * inv0, xv.y + o[df][1] * inv0);
            *reinterpret_cast<float2*>(&g_x1[idx]) = ov;
        }
        {
            size_t idx = base + (size_t)(ty + 8) * EE + col;
            float2 xv = *reinterpret_cast<const float2*>(&x[idx]);
            float2 ov = make_float2(xv.x + o[df][2] * inv1, xv.y + o[df][3] * inv1);
            *reinterpret_cast<float2*>(&g_x1[idx]) = ov;
        }
    }
}

// ---------------------------------------------------------------------------
// FFN GEMM: proven R5 tf32 path (precision-critical; stays tf32).
// out = x1 + relu(x1 @ Wf + bias). CTA 128x256, BK=32.
// ---------------------------------------------------------------------------
#define A_ST 36
#define B_ST 264
#define A_TILE (128*A_ST)
#define B_TILE (32*B_ST)
#define STAGE  (A_TILE + B_TILE)
#define GEMM_SMEM (2*STAGE*4)

__global__ void __launch_bounds__(256) ffn_gemm(const float* __restrict__ A,
                                                const float* __restrict__ W,
                                                float* __restrict__ C,
                                                const float* __restrict__ bias)
{
    extern __shared__ float sm[];
    const uint32_t sbase = smem_u32(sm);
    const int tid  = threadIdx.x;
    const int wid  = tid >> 5, lane = tid & 31;
    const int ty   = lane >> 2, tx = lane & 3;
    const int wm   = wid >> 2;
    const int wn   = wid & 3;
    const int row0 = blockIdx.y * 128;
    const int col0 = blockIdx.x * 256;

    float c[4][8][4];
    #pragma unroll
    for (int mf = 0; mf < 4; mf++)
        #pragma unroll
        for (int nf = 0; nf < 8; nf++)
            #pragma unroll
            for (int u = 0; u < 4; u++) c[mf][nf][u] = 0.f;

    auto load_tiles = [&](int st, int k0){
        uint32_t sA = sbase + st * (STAGE * 4);
        uint32_t sB = sA + A_TILE * 4;
        #pragma unroll
        for (int t = 0; t < 4; t++) {
            int s  = tid + t * 256;
            int r  = s >> 3;
            int cf = (s & 7) << 2;
            CP16(sA + (uint32_t)(r * A_ST + cf) * 4,
                 A + (size_t)(row0 + r) * EE + k0 + cf);
        }
        #pragma unroll
        for (int t = 0; t < 8; t++) {
            int s  = tid + t * 256;
            int r  = s >> 6;
            int cf = (s & 63) << 2;
            CP16(sB + (uint32_t)(r * B_ST + cf) * 4,
                 W + (size_t)(k0 + r) * EE + col0 + cf);
        }
    };

    load_tiles(0, 0);
    CP_COMMIT();

    for (int kt = 0; kt < 32; kt++) {
        const int b = kt & 1;
        if (kt + 1 < 32) {
            load_tiles(1 - b, (kt + 1) << 5);
            CP_COMMIT();
            CP_WAIT1();
        } else {
            CP_WAIT0();
        }
        __syncthreads();

        const float* As = sm + b * STAGE;
        const float* Bs = As + A_TILE;

        #pragma unroll
        for (int ks = 0; ks < 4; ks++) {
            const int k = ks << 3;
            uint32_t a[4][4];
            #pragma unroll
            for (int mf = 0; mf < 4; mf++) {
                const int rb = wm * 64 + mf * 16;
                a[mf][0] = __float_as_uint(As[(rb + ty    ) * A_ST + k + tx    ]);
                a[mf][1] = __float_as_uint(As[(rb + ty + 8) * A_ST + k + tx    ]);
                a[mf][2] = __float_as_uint(As[(rb + ty    ) * A_ST + k + tx + 4]);
                a[mf][3] = __float_as_uint(As[(rb + ty + 8) * A_ST + k + tx + 4]);
            }
            uint32_t bfr[8][2];
            #pragma unroll
            for (int nf = 0; nf < 8; nf++) {
                const int n = wn * 64 + nf * 8 + ty;
                bfr[nf][0] = __float_as_uint(Bs[(k + tx    ) * B_ST + n]);
                bfr[nf][1] = __float_as_uint(Bs[(k + tx + 4) * B_ST + n]);
            }
            #pragma unroll
            for (int mf = 0; mf < 4; mf++)
                #pragma unroll
                for (int nf = 0; nf < 8; nf++)
                    mma_tf32(c[mf][nf], a[mf][0], a[mf][1], a[mf][2], a[mf][3],
                             bfr[nf][0], bfr[nf][1]);
        }
        __syncthreads();
    }

    #pragma unroll
    for (int mf = 0; mf < 4; mf++) {
        const int r = row0 + wm * 64 + mf * 16 + ty;
        #pragma unroll
        for (int nf = 0; nf < 8; nf++) {
            const int cc = col0 + wn * 64 + nf * 8 + (tx << 1);
            float2 v0 = make_float2(c[mf][nf][0], c[mf][nf][1]);
            float2 v1 = make_float2(c[mf][nf][2], c[mf][nf][3]);
            float2 bb = *reinterpret_cast<const float2*>(bias + cc);
            float2 x0 = *reinterpret_cast<const float2*>(A + (size_t)r * EE + cc);
            float2 x1 = *reinterpret_cast<const float2*>(A + (size_t)(r + 8) * EE + cc);
            v0.x = x0.x + fmaxf(v0.x + bb.x, 0.f);
            v0.y = x0.y + fmaxf(v0.y + bb.y, 0.f);
            v1.x = x1.x + fmaxf(v1.x + bb.x, 0.f);
            v1.y = x1.y + fmaxf(v1.y + bb.y, 0.f);
            *reinterpret_cast<float2*>(C + (size_t)r * EE + cc) = v0;
            *reinterpret_cast<float2*>(C + (size_t)(r + 8) * EE + cc) = v1;
        }
    }
}

// ---------------------------------------------------------------------------
extern "C" void kernel_launch(void* const* d_in, const int* in_sizes, int n_in,
                              void* d_out, int out_size)
{
    const float* x  = (const float*)d_in[0];
    const float* Wq = (const float*)d_in[1];
    const float* Wk = (const float*)d_in[2];
    const float* Wv = (const float*)d_in[3];
    const float* Wf = (const float*)d_in[4];
    const float* bf = (const float*)d_in[5];
    float* out = (float*)d_out;

    float* gx1;
    cudaGetSymbolAddress((void**)&gx1, g_x1);

    cudaFuncSetAttribute((const void*)qkv_gemm, cudaFuncAttributeMaxDynamicSharedMemorySize, QKV_SMEM);
    cudaFuncSetAttribute((const void*)attn_tc,  cudaFuncAttributeMaxDynamicSharedMemorySize, ATTN_SMEM);
    cudaFuncSetAttribute((const void*)ffn_gemm, cudaFuncAttributeMaxDynamicSharedMemorySize, GEMM_SMEM);

    // prologue: convert + transpose
    cvt_x_kernel<<<MM*EE/1024, 256>>>(x);
    dim3 tb(32, 8), tg(32, 32);
    tpose_bf_kernel<<<tg, tb>>>(Wq, 0);
    tpose_bf_kernel<<<tg, tb>>>(Wk, 1);
    tpose_bf_kernel<<<tg, tb>>>(Wv, 2);

    // fused QKV projections (bf16 tensor cores): 12 x 32 = 384 CTAs
    qkv_gemm<<<dim3(12, MM/128), 256, QKV_SMEM>>>();

    // bf16 flash attention + residual
    attn_tc<<<dim3(TT/QT, BB*HH), 256, ATTN_SMEM>>>(x);

    // FFN (tf32) + bias + relu + residual
    ffn_gemm<<<dim3(4, MM/128), 256, GEMM_SMEM>>>(gx1, Wf, out, bf);
}

// round 12
// speedup vs baseline: 9.5962x; 1.0631x over previous
#include <cuda_runtime.h>
#include <cuda_bf16.h>
#include <cstdint>
#include <math.h>

#define BB 2
#define TT 2048
#define EE 1024
#define HH 16
#define DH 64
#define MM (BB*TT)   // 4096

// Scratch (__device__ globals; allocations are forbidden)
__device__ float          g_x1[MM*EE];          // attn+residual output (f32, FFN input)
__device__ __nv_bfloat16  g_xh[MM*EE];          // x in bf16 (QKV A operand)
__device__ __nv_bfloat16  g_qh[MM*EE];
__device__ __nv_bfloat16  g_kh[MM*EE];
__device__ __nv_bfloat16  g_vh[MM*EE];
__device__ __nv_bfloat16  g_wh3[3*EE*EE];       // Wq,Wk,Wv bf16, NATURAL [k][n] layout

// ---------------------------------------------------------------------------
// Baseline-PTX helpers (sm_80-era: mma.sync + cp.async + ldmatrix).
// ---------------------------------------------------------------------------
__device__ __forceinline__ uint32_t smem_u32(const void* p){
    uint32_t a;
    asm("{ .reg .u64 t; cvta.to.shared.u64 t, %1; cvt.u32.u64 %0, t; }":"=r"(a):"l"(p));
    return a;
}
#define CP16(dst,src)  asm volatile("cp.async.cg.shared.global [%0], [%1], 16;\n"::"r"(dst),"l"(src))
#define CP_COMMIT()    asm volatile("cp.async.commit_group;\n":::"memory")
#define CP_WAIT1()     asm volatile("cp.async.wait_group 1;\n":::"memory")
#define CP_WAIT0()     asm volatile("cp.async.wait_group 0;\n":::"memory")
#define LDSM4(r0,r1,r2,r3,addr) \
    asm volatile("ldmatrix.sync.aligned.m8n8.x4.shared.b16 {%0,%1,%2,%3}, [%4];" \
        :"=r"(r0),"=r"(r1),"=r"(r2),"=r"(r3):"r"(addr))
#define LDSM4T(r0,r1,r2,r3,addr) \
    asm volatile("ldmatrix.sync.aligned.m8n8.x4.trans.shared.b16 {%0,%1,%2,%3}, [%4];" \
        :"=r"(r0),"=r"(r1),"=r"(r2),"=r"(r3):"r"(addr))

__device__ __forceinline__ void mma_tf32(float c[4], uint32_t a0, uint32_t a1,
                                         uint32_t a2, uint32_t a3,
                                         uint32_t b0, uint32_t b1){
    asm volatile(
        "mma.sync.aligned.m16n8k8.row.col.f32.tf32.tf32.f32 "
        "{%0,%1,%2,%3}, {%4,%5,%6,%7}, {%8,%9}, {%0,%1,%2,%3};\n"
        : "+f"(c[0]), "+f"(c[1]), "+f"(c[2]), "+f"(c[3])
        : "r"(a0), "r"(a1), "r"(a2), "r"(a3), "r"(b0), "r"(b1));
}
__device__ __forceinline__ void mma_bf16(float c[4], uint32_t a0, uint32_t a1,
                                         uint32_t a2, uint32_t a3,
                                         uint32_t b0, uint32_t b1){
    asm volatile(
        "mma.sync.aligned.m16n8k16.row.col.f32.bf16.bf16.f32 "
        "{%0,%1,%2,%3}, {%4,%5,%6,%7}, {%8,%9}, {%0,%1,%2,%3};\n"
        : "+f"(c[0]), "+f"(c[1]), "+f"(c[2]), "+f"(c[3])
        : "r"(a0), "r"(a1), "r"(a2), "r"(a3), "r"(b0), "r"(b1));
}
__device__ __forceinline__ float ex2f(float x){
    float y; asm("ex2.approx.f32 %0, %1;":"=f"(y):"f"(x)); return y;
}

// ---------------------------------------------------------------------------
// Prologue (single launch): f32 -> bf16 for x, Wq, Wk, Wv (no transpose).
// 7M elements, 4 per thread.
// ---------------------------------------------------------------------------
#define XN (MM*EE)     // 4M
#define WN (EE*EE)     // 1M

__global__ void __launch_bounds__(256) cvt_all_kernel(const float* __restrict__ x,
                                                      const float* __restrict__ Wq,
                                                      const float* __restrict__ Wk,
                                                      const float* __restrict__ Wv)
{
    int i = (blockIdx.x * 256 + threadIdx.x) * 4;
    const float* src;
    __nv_bfloat16* dst;
    int off;
    if (i < XN) {
        src = x; dst = g_xh; off = i;
    } else {
        int j = i - XN;
        int slot = j >> 20;              // /WN
        off = j & (WN - 1);
        src = (slot == 0) ? Wq : (slot == 1) ? Wk : Wv;
        dst = g_wh3 + (size_t)slot * WN;
    }
    float4 v = *reinterpret_cast<const float4*>(src + off);
    __nv_bfloat162 p0 = __floats2bfloat162_rn(v.x, v.y);
    __nv_bfloat162 p1 = __floats2bfloat162_rn(v.z, v.w);
    uint2 u;
    u.x = *reinterpret_cast<uint32_t*>(&p0);
    u.y = *reinterpret_cast<uint32_t*>(&p1);
    *reinterpret_cast<uint2*>(&dst[off]) = u;
}

// ---------------------------------------------------------------------------
// bf16 QKV GEMM (fused 3 projections): C = x @ W.
// CTA 128x256, BK=32, 8 warps (2m x 4n), warp 64x64.
// A = g_xh [m][k] bf16, rows padded to 80B, non-trans LDSM.
// B = g_wh3[sel] NATURAL [k][n] bf16, staged as [32][256] rows of 512B+16 pad,
//     fragments via ldmatrix.trans (same pattern as the proven V path).
// Outputs bf16 to g_qh/g_kh/g_vh.
// ---------------------------------------------------------------------------
#define HA_BYTES (128*80)          // 10240
#define WB_ROW   528               // 256 bf16 = 512B + 16B pad
#define WB_BYTES (32*WB_ROW)       // 16896
#define HSTAGE   (HA_BYTES + WB_BYTES)   // 27136
#define QKV_SMEM (2*HSTAGE)        // 54272

__global__ void __launch_bounds__(256) qkv_gemm()
{
    extern __shared__ char smc[];
    const uint32_t sbase = smem_u32(smc);
    const int tid  = threadIdx.x;
    const int wid  = tid >> 5, lane = tid & 31;
    const int ty   = lane >> 2, tx = lane & 3;
    const int wm   = wid >> 2;
    const int wn   = wid & 3;
    const int row0 = blockIdx.y * 128;
    const int sel  = blockIdx.x >> 2;
    const int col0 = (blockIdx.x & 3) * 256;
    const __nv_bfloat16* Wt = g_wh3 + (size_t)sel * WN;   // [k][n]
    __nv_bfloat16* C = (sel == 0) ? g_qh : (sel == 1) ? g_kh : g_vh;

    float c[4][8][4];
    #pragma unroll
    for (int mf = 0; mf < 4; mf++)
        #pragma unroll
        for (int nf = 0; nf < 8; nf++)
            #pragma unroll
            for (int u = 0; u < 4; u++) c[mf][nf][u] = 0.f;

    auto load_tiles = [&](int st, int k0){
        uint32_t sA = sbase + st * HSTAGE;
        uint32_t sB = sA + HA_BYTES;
        #pragma unroll
        for (int t = 0; t < 2; t++) {               // A: 128 rows x 4 chunks (32 bf16)
            int s = tid + t * 256;
            int r = s >> 2, ch = s & 3;
            CP16(sA + (uint32_t)(r * 80 + ch * 16),
                 g_xh + (size_t)(row0 + r) * EE + k0 + ch * 8);
        }
        #pragma unroll
        for (int t = 0; t < 4; t++) {               // B: 32 k-rows x 32 chunks (256 bf16)
            int s = tid + t * 256;
            int r = s >> 5, ch = s & 31;
            CP16(sB + (uint32_t)(r * WB_ROW + ch * 16),
                 Wt + (size_t)(k0 + r) * EE + col0 + ch * 8);
        }
    };

    load_tiles(0, 0);
    CP_COMMIT();

    for (int kt = 0; kt < 32; kt++) {
        const int b = kt & 1;
        if (kt + 1 < 32) {
            load_tiles(1 - b, (kt + 1) << 5);
            CP_COMMIT();
            CP_WAIT1();
        } else {
            CP_WAIT0();
        }
        __syncthreads();

        const uint32_t sA = sbase + b * HSTAGE;
        const uint32_t sB = sA + HA_BYTES;

        #pragma unroll
        for (int ks = 0; ks < 2; ks++) {
            uint32_t a[4][4];
            #pragma unroll
            for (int mf = 0; mf < 4; mf++) {
                uint32_t row = wm * 64 + mf * 16 + (lane & 15);
                uint32_t kh  = ks * 16 + ((lane & 16) >> 1);
                LDSM4(a[mf][0], a[mf][1], a[mf][2], a[mf][3],
                      sA + row * 80 + kh * 2);
            }
            uint32_t bfr[8][2];
            #pragma unroll
            for (int p = 0; p < 4; p++) {
                uint32_t krow = ks * 16 + (lane & 15);
                uint32_t nh   = wn * 64 + p * 16 + ((lane & 16) >> 1);
                LDSM4T(bfr[2*p][0], bfr[2*p][1], bfr[2*p+1][0], bfr[2*p+1][1],
                       sB + krow * WB_ROW + nh * 2);
            }
            #pragma unroll
            for (int mf = 0; mf < 4; mf++)
                #pragma unroll
                for (int nf = 0; nf < 8; nf++)
                    mma_bf16(c[mf][nf], a[mf][0], a[mf][1], a[mf][2], a[mf][3],
                             bfr[nf][0], bfr[nf][1]);
        }
        __syncthreads();
    }

    #pragma unroll
    for (int mf = 0; mf < 4; mf++) {
        const int r = row0 + wm * 64 + mf * 16 + ty;
        #pragma unroll
        for (int nf = 0; nf < 8; nf++) {
            const int cc = col0 + wn * 64 + nf * 8 + (tx << 1);
            __nv_bfloat162 p0 = __floats2bfloat162_rn(c[mf][nf][0], c[mf][nf][1]);
            __nv_bfloat162 p1 = __floats2bfloat162_rn(c[mf][nf][2], c[mf][nf][3]);
            *reinterpret_cast<__nv_bfloat162*>(&C[(size_t)r * EE + cc]) = p0;
            *reinterpret_cast<__nv_bfloat162*>(&C[(size_t)(r + 8) * EE + cc]) = p1;
        }
    }
}

// ---------------------------------------------------------------------------
// bf16 flash attention (causal, online softmax), all-ldmatrix fragments.
// Identical to the passing R11 kernel.
// ---------------------------------------------------------------------------
#define QT 128
#define AST 72                                  // halfwords per row
#define AT_BYTES (64*AST*2)                     // 9216 per stage
#define ATTN_SMEM (4*AT_BYTES)                  // 36864: KS[2] + VS[2]

__global__ void __launch_bounds__(256, 1) attn_tc(const float* __restrict__ x)
{
    extern __shared__ char smc[];
    const uint32_t sb_KS = smem_u32(smc);               // [2][64][72]h (Q staged here too)
    const uint32_t sb_VS = sb_KS + 2 * AT_BYTES;        // [2][64][72]h

    const int tid = threadIdx.x;
    const int wid = tid >> 5, lane = tid & 31;
    const int ty = lane >> 2, tx = lane & 3;
    const int bh = blockIdx.y, b = bh >> 4, h = bh & 15;
    const int qb = blockIdx.x * QT;
    const int ktmax = (qb + QT - 1) >> 6;
    const float sc2 = 0.03125f * 1.44269504088896f;     // 1/sqrt(1024) * log2e

    // ---- stage Q (128 rows x 8 chunks of 16B) through KS area ----
    {
        const __nv_bfloat16* Qg = g_qh + (size_t)(b * TT + qb) * EE + h * DH;
        #pragma unroll
        for (int t = 0; t < 4; t++) {
            int s = tid + t * 256;          // 0..1023
            int r = s >> 3, ch = s & 7;     // 128 rows x 8 chunks
            CP16(sb_KS + (uint32_t)(r * 144 + ch * 16), Qg + (size_t)r * EE + ch * 8);
        }
        CP_COMMIT(); CP_WAIT0();
    }
    __syncthreads();

    uint32_t qa[4][4];
    #pragma unroll
    for (int kf = 0; kf < 4; kf++) {
        uint32_t row = wid * 16 + (lane & 15);
        uint32_t kh  = kf * 16 + ((lane & 16) >> 1);
        LDSM4(qa[kf][0], qa[kf][1], qa[kf][2], qa[kf][3],
              sb_KS + row * 144 + kh * 2);
    }
    __syncthreads();

    float mrow[2] = {-1e30f, -1e30f};
    float lrow[2] = {0.f, 0.f};
    float o[8][4];
    #pragma unroll
    for (int df = 0; df < 8; df++)
        #pragma unroll
        for (int u = 0; u < 4; u++) o[df][u] = 0.f;

    auto issue_tile = [&](int kt){
        const __nv_bfloat16* Kg = g_kh + (size_t)(b * TT + kt * 64) * EE + h * DH;
        const __nv_bfloat16* Vg = g_vh + (size_t)(b * TT + kt * 64) * EE + h * DH;
        uint32_t dK = sb_KS + (uint32_t)((kt & 1) * AT_BYTES);
        uint32_t dV = sb_VS + (uint32_t)((kt & 1) * AT_BYTES);
        #pragma unroll
        for (int t = 0; t < 2; t++) {
            int s = tid + t * 256;          // 0..511
            int r = s >> 3, ch = s & 7;     // 64 rows x 8 chunks
            CP16(dK + (uint32_t)(r * 144 + ch * 16), Kg + (size_t)r * EE + ch * 8);
            CP16(dV + (uint32_t)(r * 144 + ch * 16), Vg + (size_t)r * EE + ch * 8);
        }
        CP_COMMIT();
    };

    issue_tile(0);
    issue_tile(1);

    for (int kt = 0; kt <= ktmax; kt++) {
        const int bs = kt & 1;
        if (kt < ktmax) { CP_WAIT1(); } else { CP_WAIT0(); }
        __syncthreads();

        const uint32_t sK = sb_KS + bs * AT_BYTES;
        const uint32_t sV = sb_VS + bs * AT_BYTES;

        // S = Q K^T (bf16 m16n8k16)
        float s[8][4];
        #pragma unroll
        for (int nf = 0; nf < 8; nf++)
            #pragma unroll
            for (int u = 0; u < 4; u++) s[nf][u] = 0.f;
        #pragma unroll
        for (int kf = 0; kf < 4; kf++) {
            uint32_t bk[8][2];
            #pragma unroll
            for (int p = 0; p < 4; p++) {
                uint32_t row = p * 16 + (lane & 7) + ((lane & 16) >> 1);
                uint32_t kh  = kf * 16 + (lane & 8);
                LDSM4(bk[2*p][0], bk[2*p][1], bk[2*p+1][0], bk[2*p+1][1],
                      sK + row * 144 + kh * 2);
            }
            #pragma unroll
            for (int nf = 0; nf < 8; nf++)
                mma_bf16(s[nf], qa[kf][0], qa[kf][1], qa[kf][2], qa[kf][3],
                         bk[nf][0], bk[nf][1]);
        }

        // scale + causal mask + row max
        const int q0 = qb + wid * 16;
        const bool need_mask = (kt * 64 + 63) > q0;
        float pmax[2] = {-1e30f, -1e30f};
        #pragma unroll
        for (int nf = 0; nf < 8; nf++) {
            int kkb = kt * 64 + nf * 8 + 2 * tx;
            #pragma unroll
            for (int u = 0; u < 4; u++) {
                float v = s[nf][u] * sc2;
                if (need_mask) {
                    int kkg = kkb + (u & 1);
                    int qg  = q0 + ty + ((u >> 1) << 3);
                    if (kkg > qg) v = -1e30f;
                }
                s[nf][u] = v;
                pmax[u >> 1] = fmaxf(pmax[u >> 1], v);
            }
        }
        #pragma unroll
        for (int r = 0; r < 2; r++) {
            pmax[r] = fmaxf(pmax[r], __shfl_xor_sync(0xffffffffu, pmax[r], 1));
            pmax[r] = fmaxf(pmax[r], __shfl_xor_sync(0xffffffffu, pmax[r], 2));
        }
        float mn0 = fmaxf(mrow[0], pmax[0]);
        float mn1 = fmaxf(mrow[1], pmax[1]);
        float cr0 = ex2f(mrow[0] - mn0);
        float cr1 = ex2f(mrow[1] - mn1);
        mrow[0] = mn0; mrow[1] = mn1;

        // P = 2^(s-m): pack bf16 A-frags + row sums
        uint32_t pa[4][4];
        float ls[2] = {0.f, 0.f};
        #pragma unroll
        for (int nf = 0; nf < 8; nf++) {
            float p0 = ex2f(s[nf][0] - mn0);
            float p1 = ex2f(s[nf][1] - mn0);
            float p2 = ex2f(s[nf][2] - mn1);
            float p3 = ex2f(s[nf][3] - mn1);
            ls[0] += p0 + p1;
            ls[1] += p2 + p3;
            __nv_bfloat162 t0 = __floats2bfloat162_rn(p0, p1);
            __nv_bfloat162 t1 = __floats2bfloat162_rn(p2, p3);
            uint32_t lo = *reinterpret_cast<uint32_t*>(&t0);
            uint32_t hi = *reinterpret_cast<uint32_t*>(&t1);
            int kb = nf >> 1;
            if ((nf & 1) == 0) { pa[kb][0] = lo; pa[kb][1] = hi; }
            else               { pa[kb][2] = lo; pa[kb][3] = hi; }
        }
        #pragma unroll
        for (int r = 0; r < 2; r++) {
            ls[r] += __shfl_xor_sync(0xffffffffu, ls[r], 1);
            ls[r] += __shfl_xor_sync(0xffffffffu, ls[r], 2);
        }
        lrow[0] = lrow[0] * cr0 + ls[0];
        lrow[1] = lrow[1] * cr1 + ls[1];

        // rescale O, then O += P @ V  (V via ldmatrix.trans)
        #pragma unroll
        for (int df = 0; df < 8; df++) {
            o[df][0] *= cr0; o[df][1] *= cr0;
            o[df][2] *= cr1; o[df][3] *= cr1;
        }
        #pragma unroll
        for (int kb = 0; kb < 4; kb++) {
            uint32_t vb[8][2];
            #pragma unroll
            for (int dp = 0; dp < 4; dp++) {
                uint32_t row = kb * 16 + (lane & 15);
                uint32_t dhh = dp * 16 + ((lane & 16) >> 1);
                LDSM4T(vb[2*dp][0], vb[2*dp][1], vb[2*dp+1][0], vb[2*dp+1][1],
                       sV + row * 144 + dhh * 2);
            }
            #pragma unroll
            for (int df = 0; df < 8; df++)
                mma_bf16(o[df], pa[kb][0], pa[kb][1], pa[kb][2], pa[kb][3],
                         vb[df][0], vb[df][1]);
        }
        __syncthreads();
        if (kt + 2 <= ktmax) issue_tile(kt + 2);
    }

    // epilogue: normalize + residual
    const float inv0 = 1.f / lrow[0];
    const float inv1 = 1.f / lrow[1];
    const size_t base = (size_t)(b * TT + qb + wid * 16) * EE + h * DH;
    #pragma unroll
    for (int df = 0; df < 8; df++) {
        int col = df * 8 + 2 * tx;
        {
            size_t idx = base + (size_t)ty * EE + col;
            float2 xv = *reinterpret_cast<const float2*>(&x[idx]);
            float2 ov = make_float2(xv.x + o[df][0] * inv0, xv.y + o[df][1] * inv0);
            *reinterpret_cast<float2*>(&g_x1[idx]) = ov;
        }
        {
            size_t idx = base + (size_t)(ty + 8) * EE + col;
            float2 xv = *reinterpret_cast<const float2*>(&x[idx]);
            float2 ov = make_float2(xv.x + o[df][2] * inv1, xv.y + o[df][3] * inv1);
            *reinterpret_cast<float2*>(&g_x1[idx]) = ov;
        }
    }
}

// ---------------------------------------------------------------------------
// FFN GEMM: proven tf32 path (precision-critical; stays tf32).
// out = x1 + relu(x1 @ Wf + bias). CTA 128x256, BK=32.
// ---------------------------------------------------------------------------
#define A_ST 36
#define B_ST 264
#define A_TILE (128*A_ST)
#define B_TILE (32*B_ST)
#define STAGE  (A_TILE + B_TILE)
#define GEMM_SMEM (2*STAGE*4)

__global__ void __launch_bounds__(256) ffn_gemm(const float* __restrict__ A,
                                                const float* __restrict__ W,
                                                float* __restrict__ C,
                                                const float* __restrict__ bias)
{
    extern __shared__ float sm[];
    const uint32_t sbase = smem_u32(sm);
    const int tid  = threadIdx.x;
    const int wid  = tid >> 5, lane = tid & 31;
    const int ty   = lane >> 2, tx = lane & 3;
    const int wm   = wid >> 2;
    const int wn   = wid & 3;
    const int row0 = blockIdx.y * 128;
    const int col0 = blockIdx.x * 256;

    float c[4][8][4];
    #pragma unroll
    for (int mf = 0; mf < 4; mf++)
        #pragma unroll
        for (int nf = 0; nf < 8; nf++)
            #pragma unroll
            for (int u = 0; u < 4; u++) c[mf][nf][u] = 0.f;

    auto load_tiles = [&](int st, int k0){
        uint32_t sA = sbase + st * (STAGE * 4);
        uint32_t sB = sA + A_TILE * 4;
        #pragma unroll
        for (int t = 0; t < 4; t++) {
            int s  = tid + t * 256;
            int r  = s >> 3;
            int cf = (s & 7) << 2;
            CP16(sA + (uint32_t)(r * A_ST + cf) * 4,
                 A + (size_t)(row0 + r) * EE + k0 + cf);
        }
        #pragma unroll
        for (int t = 0; t < 8; t++) {
            int s  = tid + t * 256;
            int r  = s >> 6;
            int cf = (s & 63) << 2;
            CP16(sB + (uint32_t)(r * B_ST + cf) * 4,
                 W + (size_t)(k0 + r) * EE + col0 + cf);
        }
    };

    load_tiles(0, 0);
    CP_COMMIT();

    for (int kt = 0; kt < 32; kt++) {
        const int b = kt & 1;
        if (kt + 1 < 32) {
            load_tiles(1 - b, (kt + 1) << 5);
            CP_COMMIT();
            CP_WAIT1();
        } else {
            CP_WAIT0();
        }
        __syncthreads();

        const float* As = sm + b * STAGE;
        const float* Bs = As + A_TILE;

        #pragma unroll
        for (int ks = 0; ks < 4; ks++) {
            const int k = ks << 3;
            uint32_t a[4][4];
            #pragma unroll
            for (int mf = 0; mf < 4; mf++) {
                const int rb = wm * 64 + mf * 16;
                a[mf][0] = __float_as_uint(As[(rb + ty    ) * A_ST + k + tx    ]);
                a[mf][1] = __float_as_uint(As[(rb + ty + 8) * A_ST + k + tx    ]);
                a[mf][2] = __float_as_uint(As[(rb + ty    ) * A_ST + k + tx + 4]);
                a[mf][3] = __float_as_uint(As[(rb + ty + 8) * A_ST + k + tx + 4]);
            }
            uint32_t bfr[8][2];
            #pragma unroll
            for (int nf = 0; nf < 8; nf++) {
                const int n = wn * 64 + nf * 8 + ty;
                bfr[nf][0] = __float_as_uint(Bs[(k + tx    ) * B_ST + n]);
                bfr[nf][1] = __float_as_uint(Bs[(k + tx + 4) * B_ST + n]);
            }
            #pragma unroll
            for (int mf = 0; mf < 4; mf++)
                #pragma unroll
                for (int nf = 0; nf < 8; nf++)
                    mma_tf32(c[mf][nf], a[mf][0], a[mf][1], a[mf][2], a[mf][3],
                             bfr[nf][0], bfr[nf][1]);
        }
        __syncthreads();
    }

    #pragma unroll
    for (int mf = 0; mf < 4; mf++) {
        const int r = row0 + wm * 64 + mf * 16 + ty;
        #pragma unroll
        for (int nf = 0; nf < 8; nf++) {
            const int cc = col0 + wn * 64 + nf * 8 + (tx << 1);
            float2 v0 = make_float2(c[mf][nf][0], c[mf][nf][1]);
            float2 v1 = make_float2(c[mf][nf][2], c[mf][nf][3]);
            float2 bb = *reinterpret_cast<const float2*>(bias + cc);
            float2 x0 = *reinterpret_cast<const float2*>(A + (size_t)r * EE + cc);
            float2 x1 = *reinterpret_cast<const float2*>(A + (size_t)(r + 8) * EE + cc);
            v0.x = x0.x + fmaxf(v0.x + bb.x, 0.f);
            v0.y = x0.y + fmaxf(v0.y + bb.y, 0.f);
            v1.x = x1.x + fmaxf(v1.x + bb.x, 0.f);
            v1.y = x1.y + fmaxf(v1.y + bb.y, 0.f);
            *reinterpret_cast<float2*>(C + (size_t)r * EE + cc) = v0;
            *reinterpret_cast<float2*>(C + (size_t)(r + 8) * EE + cc) = v1;
        }
    }
}

// ---------------------------------------------------------------------------
extern "C" void kernel_launch(void* const* d_in, const int* in_sizes, int n_in,
                              void* d_out, int out_size)
{
    const float* x  = (const float*)d_in[0];
    const float* Wq = (const float*)d_in[1];
    const float* Wk = (const float*)d_in[2];
    const float* Wv = (const float*)d_in[3];
    const float* Wf = (const float*)d_in[4];
    const float* bf = (const float*)d_in[5];
    float* out = (float*)d_out;

    float* gx1;
    cudaGetSymbolAddress((void**)&gx1, g_x1);

    cudaFuncSetAttribute((const void*)qkv_gemm, cudaFuncAttributeMaxDynamicSharedMemorySize, QKV_SMEM);
    cudaFuncSetAttribute((const void*)attn_tc,  cudaFuncAttributeMaxDynamicSharedMemorySize, ATTN_SMEM);
    cudaFuncSetAttribute((const void*)ffn_gemm, cudaFuncAttributeMaxDynamicSharedMemorySize, GEMM_SMEM);

    // prologue: single fused f32->bf16 conversion (x + Wq + Wk + Wv)
    cvt_all_kernel<<<(XN + 3*WN) / 1024, 256>>>(x, Wq, Wk, Wv);

    // fused QKV projections (bf16 tensor cores): 12 x 32 = 384 CTAs
    qkv_gemm<<<dim3(12, MM/128), 256, QKV_SMEM>>>();

    // bf16 flash attention + residual
    attn_tc<<<dim3(TT/QT, BB*HH), 256, ATTN_SMEM>>>(x);

    // FFN (tf32) + bias + relu + residual
    ffn_gemm<<<dim3(4, MM/128), 256, GEMM_SMEM>>>(gx1, Wf, out, bf);
}